// round 6
// baseline (speedup 1.0000x reference)
#include <cuda_runtime.h>
#include <cuda_fp16.h>
#include <cstdint>
#include <math.h>

#define Bb     8
#define NN     4096
#define RR     32768
#define DD     256
#define D2     512
#define HEADS  8
#define DK     32
#define EPS    1e-5f

// ---------------- scratch (device globals; no runtime allocation) -----------
__device__ __align__(16) __half g_n1h [RR * DD];
__device__ __align__(16) float  g_n2  [RR * DD];
__device__ __align__(16) __half g_w1h [DD * D2];       // W1^T [n][k] fp16
__device__ __align__(16) __half g_b2h [Bb * D2 * DD];  // W2eff [b][o][c] fp16
__device__ __align__(16) float  g_part [Bb * 8 * DD];
__device__ __align__(16) float  g_ksum [Bb * DD];
__device__ __align__(16) float  g_Spart[8 * Bb * HEADS * DK * DK];
__device__ __align__(16) float  g_ctx  [Bb * HEADS * DK * DK];

// ---------------- helpers ----------------------------------------------------
__device__ __forceinline__ uint32_t s2u(const void* p) {
    uint32_t a;
    asm("{ .reg .u64 t; cvta.to.shared.u64 t, %1; cvt.u32.u64 %0, t; }"
        : "=r"(a) : "l"(p));
    return a;
}
__device__ __forceinline__ void cvt8(const float4& a, const float4& b, uint4& o) {
    __half2 h0 = __floats2half2_rn(a.x, a.y);
    __half2 h1 = __floats2half2_rn(a.z, a.w);
    __half2 h2 = __floats2half2_rn(b.x, b.y);
    __half2 h3 = __floats2half2_rn(b.z, b.w);
    o.x = *reinterpret_cast<uint32_t*>(&h0);
    o.y = *reinterpret_cast<uint32_t*>(&h1);
    o.z = *reinterpret_cast<uint32_t*>(&h2);
    o.w = *reinterpret_cast<uint32_t*>(&h3);
}
__device__ __forceinline__ void ldsm4(uint32_t* r, uint32_t addr) {
    asm volatile("ldmatrix.sync.aligned.m8n8.x4.shared.b16 {%0,%1,%2,%3}, [%4];"
                 : "=r"(r[0]), "=r"(r[1]), "=r"(r[2]), "=r"(r[3]) : "r"(addr));
}
__device__ __forceinline__ void mma16816(float* c, const uint32_t* a,
                                         const uint32_t* b) {
    asm volatile(
        "mma.sync.aligned.m16n8k16.row.col.f32.f16.f16.f32 "
        "{%0,%1,%2,%3}, {%4,%5,%6,%7}, {%8,%9}, {%0,%1,%2,%3};"
        : "+f"(c[0]), "+f"(c[1]), "+f"(c[2]), "+f"(c[3])
        : "r"(a[0]), "r"(a[1]), "r"(a[2]), "r"(a[3]), "r"(b[0]), "r"(b[1]));
}
__device__ __forceinline__ void cpa16(uint32_t dst, const void* src) {
    asm volatile("cp.async.ca.shared.global [%0], [%1], 16;" :: "r"(dst), "l"(src));
}
#define CP_COMMIT() asm volatile("cp.async.commit_group;")
#define CP_WAIT0()  asm volatile("cp.async.wait_group 0;")

// swizzled byte offset: rows of 32 fp16 (64B), 4 chunks of 16B, XOR swizzle
__device__ __forceinline__ uint32_t sw_off(int row, int cch) {
    return (uint32_t)(row * 64 + ((cch ^ ((row >> 1) & 3)) << 4));
}

// ============ GEMM1 fused: n1h = fp16( LN(x1 @ W1 + b1) ) ====================
// CTA: 64 rows x 256 cols (full row), K=512 in 16 chunks of 32.
// 8 warps, 1m x 8n, warp tile 64x32. 2-stage pipeline, cp.async for B.
__global__ __launch_bounds__(256, 2) void gemm1_ln_k(
    const float* __restrict__ x1, const __half* __restrict__ w1,
    const float* __restrict__ bias, const float* __restrict__ g,
    const float* __restrict__ bvec, __half* __restrict__ n1h)
{
    __shared__ __align__(16) __half sA[2][64 * 32];
    __shared__ __align__(16) __half sB[2][256 * 32];
    __shared__ float sBias[256], sG[256], sBv[256];
    __shared__ float rsum[64], rsq[64];

    const int t = threadIdx.x, lane = t & 31, wid = t >> 5;
    const int wn = wid * 32;
    const int row0 = blockIdx.x * 64;

    sBias[t] = bias[t]; sG[t] = g[t]; sBv[t] = bvec[t];
    if (t < 64) { rsum[t] = 0.f; rsq[t] = 0.f; }

    const uint32_t uA = s2u(sA), uB = s2u(sB);

    // staging maps
    const int ar = t >> 2, aq = t & 3;                  // A: row, 8-col chunk
    const float* aptr = x1 + (size_t)(row0 + ar) * D2 + aq * 8;
    const uint32_t staA = sw_off(ar, aq);
    const __half* bptr = w1 + (size_t)t * D2;           // B: n-row = t

    float acc[4][4][4];
#pragma unroll
    for (int i = 0; i < 4; i++)
#pragma unroll
        for (int j = 0; j < 4; j++)
#pragma unroll
            for (int k = 0; k < 4; k++) acc[i][j][k] = 0.f;

    const int ti = lane >> 3, tr = lane & 7;
    const int a_dm = (ti & 1) * 8, a_dkc = ti >> 1;
    const int b_dn = (ti >> 1) * 8, b_dkc = ti & 1;

    // prologue: stage 0
    {
        float4 a0 = *(const float4*)(aptr);
        float4 a1 = *(const float4*)(aptr + 4);
        uint4 av; cvt8(a0, a1, av);
        *(uint4*)((char*)sA[0] + staA) = av;
#pragma unroll
        for (int c = 0; c < 4; c++)
            cpa16(uB + sw_off(t, c), bptr + c * 8);
        CP_COMMIT();
    }

    const int nk = D2 / 32;   // 16
    float4 na0, na1;
    for (int kk = 0; kk < nk; kk++) {
        const int buf = kk & 1, nxt = buf ^ 1;
        const bool has = (kk + 1) < nk;
        CP_WAIT0();
        __syncthreads();
        // launch next-stage B cp.async + A global loads
        if (has) {
            const int k0 = (kk + 1) * 32;
#pragma unroll
            for (int c = 0; c < 4; c++)
                cpa16(uB + nxt * 16384 + sw_off(t, c), bptr + k0 + c * 8);
            CP_COMMIT();
            na0 = *(const float4*)(aptr + k0);
            na1 = *(const float4*)(aptr + k0 + 4);
        }
        // compute stage buf
        const uint32_t bA = uA + buf * 4096, bB = uB + buf * 16384;
#pragma unroll
        for (int ks = 0; ks < 2; ks++) {
            uint32_t af[4][4], bf[2][4];
#pragma unroll
            for (int mf = 0; mf < 4; mf++)
                ldsm4(af[mf], bA + sw_off(mf * 16 + a_dm + tr, ks * 2 + a_dkc));
#pragma unroll
            for (int g2 = 0; g2 < 2; g2++)
                ldsm4(bf[g2], bB + sw_off(wn + g2 * 16 + b_dn + tr, ks * 2 + b_dkc));
#pragma unroll
            for (int mf = 0; mf < 4; mf++)
#pragma unroll
                for (int nf = 0; nf < 4; nf++)
                    mma16816(acc[mf][nf], af[mf], &bf[nf >> 1][(nf & 1) * 2]);
        }
        if (has) {
            uint4 av; cvt8(na0, na1, av);
            *(uint4*)((char*)sA[nxt] + staA) = av;
        }
    }

    // ---- epilogue: bias + LN over 256, write fp16 ----
    const int rl = lane >> 2, cl = (lane & 3) * 2;
#pragma unroll
    for (int mf = 0; mf < 4; mf++) {
        float s0 = 0.f, q0 = 0.f, s1 = 0.f, q1 = 0.f;
#pragma unroll
        for (int nf = 0; nf < 4; nf++) {
            const int c = wn + cl + nf * 8;
            float v0 = acc[mf][nf][0] + sBias[c];
            float v1 = acc[mf][nf][1] + sBias[c + 1];
            float v2 = acc[mf][nf][2] + sBias[c];
            float v3 = acc[mf][nf][3] + sBias[c + 1];
            acc[mf][nf][0] = v0; acc[mf][nf][1] = v1;
            acc[mf][nf][2] = v2; acc[mf][nf][3] = v3;
            s0 += v0 + v1; q0 += v0 * v0 + v1 * v1;
            s1 += v2 + v3; q1 += v2 * v2 + v3 * v3;
        }
#pragma unroll
        for (int o = 1; o <= 2; o <<= 1) {
            s0 += __shfl_xor_sync(0xffffffffu, s0, o);
            q0 += __shfl_xor_sync(0xffffffffu, q0, o);
            s1 += __shfl_xor_sync(0xffffffffu, s1, o);
            q1 += __shfl_xor_sync(0xffffffffu, q1, o);
        }
        if ((lane & 3) == 0) {
            atomicAdd(&rsum[rl + mf * 16], s0);
            atomicAdd(&rsq [rl + mf * 16], q0);
            atomicAdd(&rsum[rl + mf * 16 + 8], s1);
            atomicAdd(&rsq [rl + mf * 16 + 8], q1);
        }
    }
    __syncthreads();
#pragma unroll
    for (int mf = 0; mf < 4; mf++) {
        const int r0 = rl + mf * 16, r1 = r0 + 8;
        const float m0 = rsum[r0] * (1.f / DD);
        const float i0 = rsqrtf(rsq[r0] * (1.f / DD) - m0 * m0 + EPS);
        const float m1 = rsum[r1] * (1.f / DD);
        const float i1 = rsqrtf(rsq[r1] * (1.f / DD) - m1 * m1 + EPS);
        __half* d0 = n1h + (size_t)(row0 + r0) * DD;
        __half* d1 = n1h + (size_t)(row0 + r1) * DD;
#pragma unroll
        for (int nf = 0; nf < 4; nf++) {
            const int c = wn + cl + nf * 8;
            __half2 h0 = __floats2half2_rn(
                (acc[mf][nf][0] - m0) * i0 * sG[c] + sBv[c],
                (acc[mf][nf][1] - m0) * i0 * sG[c + 1] + sBv[c + 1]);
            __half2 h1 = __floats2half2_rn(
                (acc[mf][nf][2] - m1) * i1 * sG[c] + sBv[c],
                (acc[mf][nf][3] - m1) * i1 * sG[c + 1] + sBv[c + 1]);
            *(__half2*)(d0 + c) = h0;
            *(__half2*)(d1 + c) = h1;
        }
    }
}

// ============ GEMM2 fused: out = x1 + LN(n1h @ W2eff[b] + b2) ================
// CTA: 64 rows x 512 cols (full row), K=256 in 8 chunks of 32.
// 8 warps, 1m x 8n, warp tile 64x64. 2-stage pipeline, cp.async A & B.
#define G2_SA_ST  4096
#define G2_SB_ST  32768
#define G2_SA     0
#define G2_SB     (2 * G2_SA_ST)
#define G2_VEC    (G2_SB + 2 * G2_SB_ST)      // sBias/sG/sBv: 3*512 floats
#define G2_RED    (G2_VEC + 3 * 512 * 4)      // rsum/rsq: 2*64 floats
#define G2_SMEM   (G2_RED + 2 * 64 * 4)

__global__ __launch_bounds__(256, 1) void gemm2_ln_k(
    const __half* __restrict__ n1h, const __half* __restrict__ b2,
    const float* __restrict__ bias, const float* __restrict__ g,
    const float* __restrict__ bvec, const float* __restrict__ x1,
    float* __restrict__ outp)
{
    extern __shared__ char smem[];
    const uint32_t uA = s2u(smem) + G2_SA;
    const uint32_t uB = s2u(smem) + G2_SB;
    float* sBias = (float*)(smem + G2_VEC);
    float* sG    = sBias + 512;
    float* sBv   = sG + 512;
    float* rsum  = (float*)(smem + G2_RED);
    float* rsq   = rsum + 64;

    const int t = threadIdx.x, lane = t & 31, wid = t >> 5;
    const int wn = wid * 64;
    const int row0 = blockIdx.x * 64;
    const int b = blockIdx.x >> 6;             // 64 CTAs per batch
    const __half* Bp = b2 + (size_t)b * D2 * DD;

    sBias[t] = bias[t]; sBias[t + 256] = bias[t + 256];
    sG[t] = g[t];       sG[t + 256]    = g[t + 256];
    sBv[t] = bvec[t];   sBv[t + 256]   = bvec[t + 256];
    if (t < 64) { rsum[t] = 0.f; rsq[t] = 0.f; }

    const int ar = t >> 2, aq = t & 3;
    const __half* aptr = n1h + (size_t)(row0 + ar) * DD + aq * 8;
    const uint32_t staA = sw_off(ar, aq);
    const __half* bptr0 = Bp + (size_t)t * DD;
    const __half* bptr1 = Bp + (size_t)(t + 256) * DD;

    float acc[4][8][4];
#pragma unroll
    for (int i = 0; i < 4; i++)
#pragma unroll
        for (int j = 0; j < 8; j++)
#pragma unroll
            for (int k = 0; k < 4; k++) acc[i][j][k] = 0.f;

    const int ti = lane >> 3, tr = lane & 7;
    const int a_dm = (ti & 1) * 8, a_dkc = ti >> 1;
    const int b_dn = (ti >> 1) * 8, b_dkc = ti & 1;

    // prologue stage 0
    {
        cpa16(uA + staA, aptr);
#pragma unroll
        for (int c = 0; c < 4; c++) {
            cpa16(uB + sw_off(t, c), bptr0 + c * 8);
            cpa16(uB + sw_off(t + 256, c), bptr1 + c * 8);
        }
        CP_COMMIT();
    }

    const int nk = DD / 32;    // 8
    for (int kk = 0; kk < nk; kk++) {
        const int buf = kk & 1, nxt = buf ^ 1;
        const bool has = (kk + 1) < nk;
        CP_WAIT0();
        __syncthreads();
        if (has) {
            const int k0 = (kk + 1) * 32;
            cpa16(uA + nxt * G2_SA_ST + staA, aptr + k0);
#pragma unroll
            for (int c = 0; c < 4; c++) {
                cpa16(uB + nxt * G2_SB_ST + sw_off(t, c), bptr0 + k0 + c * 8);
                cpa16(uB + nxt * G2_SB_ST + sw_off(t + 256, c), bptr1 + k0 + c * 8);
            }
            CP_COMMIT();
        }
        const uint32_t bA = uA + buf * G2_SA_ST, bB = uB + buf * G2_SB_ST;
#pragma unroll
        for (int ks = 0; ks < 2; ks++) {
            uint32_t af[4][4], bf[4][4];
#pragma unroll
            for (int mf = 0; mf < 4; mf++)
                ldsm4(af[mf], bA + sw_off(mf * 16 + a_dm + tr, ks * 2 + a_dkc));
#pragma unroll
            for (int g2 = 0; g2 < 4; g2++)
                ldsm4(bf[g2], bB + sw_off(wn + g2 * 16 + b_dn + tr, ks * 2 + b_dkc));
#pragma unroll
            for (int mf = 0; mf < 4; mf++)
#pragma unroll
                for (int nf = 0; nf < 8; nf++)
                    mma16816(acc[mf][nf], af[mf], &bf[nf >> 1][(nf & 1) * 2]);
        }
    }

    // ---- epilogue: bias + LN over 512 + residual ----
    const int rl = lane >> 2, cl = (lane & 3) * 2;
#pragma unroll
    for (int mf = 0; mf < 4; mf++) {
        float s0 = 0.f, q0 = 0.f, s1 = 0.f, q1 = 0.f;
#pragma unroll
        for (int nf = 0; nf < 8; nf++) {
            const int c = wn + cl + nf * 8;
            float v0 = acc[mf][nf][0] + sBias[c];
            float v1 = acc[mf][nf][1] + sBias[c + 1];
            float v2 = acc[mf][nf][2] + sBias[c];
            float v3 = acc[mf][nf][3] + sBias[c + 1];
            acc[mf][nf][0] = v0; acc[mf][nf][1] = v1;
            acc[mf][nf][2] = v2; acc[mf][nf][3] = v3;
            s0 += v0 + v1; q0 += v0 * v0 + v1 * v1;
            s1 += v2 + v3; q1 += v2 * v2 + v3 * v3;
        }
#pragma unroll
        for (int o = 1; o <= 2; o <<= 1) {
            s0 += __shfl_xor_sync(0xffffffffu, s0, o);
            q0 += __shfl_xor_sync(0xffffffffu, q0, o);
            s1 += __shfl_xor_sync(0xffffffffu, s1, o);
            q1 += __shfl_xor_sync(0xffffffffu, q1, o);
        }
        if ((lane & 3) == 0) {
            atomicAdd(&rsum[rl + mf * 16], s0);
            atomicAdd(&rsq [rl + mf * 16], q0);
            atomicAdd(&rsum[rl + mf * 16 + 8], s1);
            atomicAdd(&rsq [rl + mf * 16 + 8], q1);
        }
    }
    __syncthreads();
#pragma unroll
    for (int mf = 0; mf < 4; mf++) {
        const int r0 = rl + mf * 16, r1 = r0 + 8;
        const float m0 = rsum[r0] * (1.f / D2);
        const float i0 = rsqrtf(rsq[r0] * (1.f / D2) - m0 * m0 + EPS);
        const float m1 = rsum[r1] * (1.f / D2);
        const float i1 = rsqrtf(rsq[r1] * (1.f / D2) - m1 * m1 + EPS);
        const float* x0 = x1 + (size_t)(row0 + r0) * D2;
        const float* x1p = x1 + (size_t)(row0 + r1) * D2;
        float* d0 = outp + (size_t)(row0 + r0) * D2;
        float* d1 = outp + (size_t)(row0 + r1) * D2;
#pragma unroll
        for (int nf = 0; nf < 8; nf++) {
            const int c = wn + cl + nf * 8;
            float2 xa = *(const float2*)(x0 + c);
            float2 xb = *(const float2*)(x1p + c);
            float2 o0, o1;
            o0.x = xa.x + (acc[mf][nf][0] - m0) * i0 * sG[c] + sBv[c];
            o0.y = xa.y + (acc[mf][nf][1] - m0) * i0 * sG[c + 1] + sBv[c + 1];
            o1.x = xb.x + (acc[mf][nf][2] - m1) * i1 * sG[c] + sBv[c];
            o1.y = xb.y + (acc[mf][nf][3] - m1) * i1 * sG[c + 1] + sBv[c + 1];
            *(float2*)(d0 + c) = o0;
            *(float2*)(d1 + c) = o1;
        }
    }
}

// ---------------- LN(x2) -> n2 (fp32) ----------------------------------------
__global__ __launch_bounds__(256) void ln_f32_k(
    const float* __restrict__ src, const float* __restrict__ g,
    const float* __restrict__ b, float* __restrict__ dst)
{
    const int row  = (blockIdx.x * blockDim.x + threadIdx.x) >> 5;
    const int lane = threadIdx.x & 31;
    const float* p = src + (size_t)row * DD + lane * 8;
    float4 a = *(const float4*)p;
    float4 c = *(const float4*)(p + 4);

    float s = a.x + a.y + a.z + a.w + c.x + c.y + c.z + c.w;
#pragma unroll
    for (int o = 16; o; o >>= 1) s += __shfl_xor_sync(0xffffffffu, s, o);
    const float mean = s * (1.0f / DD);

    float ax = a.x - mean, ay = a.y - mean, az = a.z - mean, aw = a.w - mean;
    float cx = c.x - mean, cy = c.y - mean, cz = c.z - mean, cw = c.w - mean;
    float s2 = ax*ax + ay*ay + az*az + aw*aw + cx*cx + cy*cy + cz*cz + cw*cw;
#pragma unroll
    for (int o = 16; o; o >>= 1) s2 += __shfl_xor_sync(0xffffffffu, s2, o);
    const float rstd = rsqrtf(s2 * (1.0f / DD) + EPS);

    const int ci = lane * 8;
    float4 g0 = *(const float4*)(g + ci);
    float4 g1 = *(const float4*)(g + ci + 4);
    float4 b0 = *(const float4*)(b + ci);
    float4 b1 = *(const float4*)(b + ci + 4);
    float4 o0, o1;
    o0.x = ax*rstd*g0.x + b0.x; o0.y = ay*rstd*g0.y + b0.y;
    o0.z = az*rstd*g0.z + b0.z; o0.w = aw*rstd*g0.w + b0.w;
    o1.x = cx*rstd*g1.x + b1.x; o1.y = cy*rstd*g1.y + b1.y;
    o1.z = cz*rstd*g1.z + b1.z; o1.w = cw*rstd*g1.w + b1.w;
    float* q = dst + (size_t)row * DD + ci;
    *(float4*)q       = o0;
    *(float4*)(q + 4) = o1;
}

// ---------------- ctx partials + fused ksum partials -------------------------
__global__ __launch_bounds__(256) void ctx_part_k(
    const float* __restrict__ n2, float* __restrict__ Spart,
    float* __restrict__ part)
{
    __shared__ __align__(16) float sm_e[2][8][32];
    __shared__ __align__(16) float sm_q[2][8][32];
    __shared__ float sred[8][32];

    const int chunk = blockIdx.x;   // 8
    const int h     = blockIdx.y;   // 8
    const int b     = blockIdx.z;   // 8
    const int t     = threadIdx.x;
    const int lane  = t & 31;
    const int w     = t >> 5;
    const int tx    = t & 15;
    const int ty    = t >> 4;

    float a00 = 0.f, a01 = 0.f, a10 = 0.f, a11 = 0.f, ks = 0.f;
    const float* base = n2 + ((size_t)b * NN + chunk * 512) * DD + h * DK;

    for (int nb = 0; nb < 512; nb += 8) {
        const int p = (nb >> 3) & 1;
        float e = __expf(base[(size_t)(nb + w) * DD + lane]);
        ks += e;
        float qs = e;
#pragma unroll
        for (int o = 16; o; o >>= 1) qs += __shfl_xor_sync(0xffffffffu, qs, o);
        sm_e[p][w][lane] = e;
        sm_q[p][w][lane] = e / qs;
        __syncthreads();
#pragma unroll
        for (int j = 0; j < 8; j++) {
            float2 qd = *(const float2*)&sm_q[p][j][ty * 2];
            float2 ke = *(const float2*)&sm_e[p][j][tx * 2];
            a00 += qd.x * ke.x; a01 += qd.x * ke.y;
            a10 += qd.y * ke.x; a11 += qd.y * ke.y;
        }
    }

    sred[w][lane] = ks;
    __syncthreads();
    if (t < 32) {
        float s = 0.f;
#pragma unroll
        for (int j = 0; j < 8; j++) s += sred[j][t];
        part[(b * 8 + chunk) * DD + h * DK + t] = s;
    }

    float* o = Spart + (size_t)(chunk * 64 + b * 8 + h) * (DK * DK);
    const int d = ty * 2, e = tx * 2;
    o[d * 32 + e]           = a00;
    o[d * 32 + e + 1]       = a01;
    o[(d + 1) * 32 + e]     = a10;
    o[(d + 1) * 32 + e + 1] = a11;
}

__global__ void ksum_reduce_k(const float* __restrict__ part,
                              float* __restrict__ ksum)
{
    const int b = blockIdx.x, c = threadIdx.x;
    float s = 0.f;
#pragma unroll
    for (int j = 0; j < 8; j++) s += part[(b * 8 + j) * DD + c];
    ksum[b * DD + c] = s;
}

__global__ __launch_bounds__(1024) void ctx_final_k(
    const float* __restrict__ Spart, const float* __restrict__ ksum,
    float* __restrict__ ctx)
{
    const int bh = blockIdx.x;
    const int t  = threadIdx.x;   // d*32+e
    const int b  = bh >> 3, h = bh & 7;
    const int e  = t & 31;
    float s = 0.f;
#pragma unroll
    for (int ch = 0; ch < 8; ch++)
        s += Spart[(size_t)(ch * 64 + bh) * (DK * DK) + t];
    ctx[(size_t)bh * (DK * DK) + t] = s / ksum[b * DD + h * DK + e];
}

// ---------------- W2eff[b][o][c=h*32+e] = sum_d ctx[b,h,d,e]*rw[o][h*32+d] ---
__global__ __launch_bounds__(256) void w2eff_k(
    const float* __restrict__ ctx, const float* __restrict__ rw,
    __half* __restrict__ b2h)
{
    extern __shared__ float ws[];
    float* ctxs = ws;          // 8192
    float* rws  = ws + 8192;   // 32 x 256
    const int b  = blockIdx.x;
    const int o0 = blockIdx.y * 32;
    const int t  = threadIdx.x;

    const float* cs = ctx + (size_t)b * HEADS * DK * DK;
    for (int i = t; i < HEADS * DK * DK; i += 256) ctxs[i] = cs[i];
    for (int i = t; i < 32 * 256; i += 256)
        rws[i] = rw[(size_t)(o0 + (i >> 8)) * DD + (i & 255)];
    __syncthreads();

    const int h = t >> 5, e = t & 31;
    const float* cbase = ctxs + h * (DK * DK) + e;
    for (int o = 0; o < 32; o++) {
        float acc = 0.f;
        const float* rb = rws + (o << 8) + h * DK;
#pragma unroll
        for (int d = 0; d < 32; d++) acc += cbase[d * 32] * rb[d];
        b2h[((size_t)b * D2 + o0 + o) * DD + t] = __float2half_rn(acc);
    }
}

// ---------------- W1 transpose + fp16 conversion -----------------------------
__global__ void convert_w1_k(const float* __restrict__ W,
                             __half* __restrict__ wh)
{
    __shared__ float tile[32][33];
    const int n0 = blockIdx.x * 32;
    const int k0 = blockIdx.y * 32;
    const int x = threadIdx.x, y = threadIdx.y;  // 32x8
#pragma unroll
    for (int i = 0; i < 32; i += 8)
        tile[y + i][x] = W[(size_t)(k0 + y + i) * DD + n0 + x];
    __syncthreads();
#pragma unroll
    for (int i = 0; i < 32; i += 8)
        wh[(size_t)(n0 + y + i) * D2 + k0 + x] = __float2half_rn(tile[x][y + i]);
}

// ---------------- host launch ------------------------------------------------
extern "C" void kernel_launch(void* const* d_in, const int* in_sizes, int n_in,
                              void* d_out, int out_size)
{
    const float* x1        = (const float*)d_in[0];
    const float* x2        = (const float*)d_in[1];
    const float* linear_w  = (const float*)d_in[2];
    const float* linear_b  = (const float*)d_in[3];
    const float* ln1_g     = (const float*)d_in[4];
    const float* ln1_b     = (const float*)d_in[5];
    const float* reproj_w  = (const float*)d_in[6];
    const float* reproj_b  = (const float*)d_in[7];
    const float* ln_attn_g = (const float*)d_in[8];
    const float* ln_attn_b = (const float*)d_in[9];
    float* out = (float*)d_out;

    float *n2, *part, *ksum, *Spart, *ctx;
    __half *n1h, *w1h, *b2h;
    cudaGetSymbolAddress((void**)&n1h,  g_n1h);
    cudaGetSymbolAddress((void**)&n2,   g_n2);
    cudaGetSymbolAddress((void**)&w1h,  g_w1h);
    cudaGetSymbolAddress((void**)&b2h,  g_b2h);
    cudaGetSymbolAddress((void**)&part, g_part);
    cudaGetSymbolAddress((void**)&ksum, g_ksum);
    cudaGetSymbolAddress((void**)&Spart,g_Spart);
    cudaGetSymbolAddress((void**)&ctx,  g_ctx);

    cudaFuncSetAttribute(gemm2_ln_k, cudaFuncAttributeMaxDynamicSharedMemorySize,
                         G2_SMEM);
    cudaFuncSetAttribute(w2eff_k, cudaFuncAttributeMaxDynamicSharedMemorySize,
                         65536);

    // prep: W1 transpose/convert + LN(x2)
    convert_w1_k<<<dim3(DD / 32, D2 / 32), dim3(32, 8)>>>(linear_w, w1h);
    ln_f32_k<<<RR / 8, 256>>>(x2, ln1_g, ln1_b, n2);

    // GEMM1 + bias + LN fused -> n1h (fp16)
    gemm1_ln_k<<<RR / 64, 256>>>(x1, w1h, linear_b, ln1_g, ln1_b, n1h);

    // attention statistics
    ctx_part_k<<<dim3(8, HEADS, Bb), 256>>>(n2, Spart, part);
    ksum_reduce_k<<<Bb, DD>>>(part, ksum);
    ctx_final_k<<<Bb * HEADS, DK * DK>>>(Spart, ksum, ctx);

    // effective reprojection weights per batch
    w2eff_k<<<dim3(Bb, D2 / 32), 256, 65536>>>(ctx, reproj_w, b2h);

    // GEMM2 + bias + LN + residual fused -> out
    gemm2_ln_k<<<RR / 64, 256, G2_SMEM>>>(n1h, b2h, reproj_b, ln_attn_g,
                                          ln_attn_b, x1, out);
}

// round 7
// speedup vs baseline: 1.1240x; 1.1240x over previous
#include <cuda_runtime.h>
#include <cuda_fp16.h>
#include <cstdint>
#include <math.h>

#define Bb     8
#define NN     4096
#define RR     32768
#define DD     256
#define D2     512
#define HEADS  8
#define DK     32
#define EPS    1e-5f

// ---------------- scratch (device globals; no runtime allocation) -----------
__device__ __align__(16) __half g_n1h [RR * DD];
__device__ __align__(16) __half g_E   [RR * DD];        // exp(LN(x2)) fp16
__device__ __align__(16) __half g_Y   [RR * DD];        // E/qsum fp16
__device__ __align__(16) __half g_w1h [DD * D2];        // W1^T [n][k] fp16
__device__ __align__(16) __half g_b2h [Bb * D2 * DD];   // W2eff [b][o][c] fp16
__device__ __align__(16) float  g_part [Bb * 32 * DD];
__device__ __align__(16) float  g_ksum [Bb * DD];
__device__ __align__(16) float  g_Spart[32 * Bb * HEADS * DK * DK];
__device__ __align__(16) float  g_ctx  [Bb * HEADS * DK * DK];

// ---------------- helpers ----------------------------------------------------
__device__ __forceinline__ uint32_t s2u(const void* p) {
    uint32_t a;
    asm("{ .reg .u64 t; cvta.to.shared.u64 t, %1; cvt.u32.u64 %0, t; }"
        : "=r"(a) : "l"(p));
    return a;
}
__device__ __forceinline__ void cvt8(const float4& a, const float4& b, uint4& o) {
    __half2 h0 = __floats2half2_rn(a.x, a.y);
    __half2 h1 = __floats2half2_rn(a.z, a.w);
    __half2 h2 = __floats2half2_rn(b.x, b.y);
    __half2 h3 = __floats2half2_rn(b.z, b.w);
    o.x = *reinterpret_cast<uint32_t*>(&h0);
    o.y = *reinterpret_cast<uint32_t*>(&h1);
    o.z = *reinterpret_cast<uint32_t*>(&h2);
    o.w = *reinterpret_cast<uint32_t*>(&h3);
}
__device__ __forceinline__ void ldsm4(uint32_t* r, uint32_t addr) {
    asm volatile("ldmatrix.sync.aligned.m8n8.x4.shared.b16 {%0,%1,%2,%3}, [%4];"
                 : "=r"(r[0]), "=r"(r[1]), "=r"(r[2]), "=r"(r[3]) : "r"(addr));
}
__device__ __forceinline__ void mma16816(float* c, const uint32_t* a,
                                         const uint32_t* b) {
    asm volatile(
        "mma.sync.aligned.m16n8k16.row.col.f32.f16.f16.f32 "
        "{%0,%1,%2,%3}, {%4,%5,%6,%7}, {%8,%9}, {%0,%1,%2,%3};"
        : "+f"(c[0]), "+f"(c[1]), "+f"(c[2]), "+f"(c[3])
        : "r"(a[0]), "r"(a[1]), "r"(a[2]), "r"(a[3]), "r"(b[0]), "r"(b[1]));
}
__device__ __forceinline__ void cpa16(uint32_t dst, const void* src) {
    asm volatile("cp.async.ca.shared.global [%0], [%1], 16;" :: "r"(dst), "l"(src));
}
#define CP_COMMIT() asm volatile("cp.async.commit_group;")
#define CP_WAIT0()  asm volatile("cp.async.wait_group 0;")

// swizzled byte offset: rows of 32 fp16 (64B), 4 chunks of 16B, XOR swizzle
__device__ __forceinline__ uint32_t sw_off(int row, int cch) {
    return (uint32_t)(row * 64 + ((cch ^ ((row >> 1) & 3)) << 4));
}

// ============ GEMM1 fused: n1h = fp16( LN(x1 @ W1 + b1) ) ====================
__global__ __launch_bounds__(256, 2) void gemm1_ln_k(
    const float* __restrict__ x1, const __half* __restrict__ w1,
    const float* __restrict__ bias, const float* __restrict__ g,
    const float* __restrict__ bvec, __half* __restrict__ n1h)
{
    __shared__ __align__(16) __half sA[2][64 * 32];
    __shared__ __align__(16) __half sB[2][256 * 32];
    __shared__ float sBias[256], sG[256], sBv[256];
    __shared__ float rsum[64], rsq[64];

    const int t = threadIdx.x, lane = t & 31, wid = t >> 5;
    const int wn = wid * 32;
    const int row0 = blockIdx.x * 64;

    sBias[t] = bias[t]; sG[t] = g[t]; sBv[t] = bvec[t];
    if (t < 64) { rsum[t] = 0.f; rsq[t] = 0.f; }

    const uint32_t uA = s2u(sA), uB = s2u(sB);

    const int ar = t >> 2, aq = t & 3;
    const float* aptr = x1 + (size_t)(row0 + ar) * D2 + aq * 8;
    const uint32_t staA = sw_off(ar, aq);
    const __half* bptr = w1 + (size_t)t * D2;

    float acc[4][4][4];
#pragma unroll
    for (int i = 0; i < 4; i++)
#pragma unroll
        for (int j = 0; j < 4; j++)
#pragma unroll
            for (int k = 0; k < 4; k++) acc[i][j][k] = 0.f;

    const int ti = lane >> 3, tr = lane & 7;
    const int a_dm = (ti & 1) * 8, a_dkc = ti >> 1;
    const int b_dn = (ti >> 1) * 8, b_dkc = ti & 1;

    {
        float4 a0 = *(const float4*)(aptr);
        float4 a1 = *(const float4*)(aptr + 4);
        uint4 av; cvt8(a0, a1, av);
        *(uint4*)((char*)sA[0] + staA) = av;
#pragma unroll
        for (int c = 0; c < 4; c++)
            cpa16(uB + sw_off(t, c), bptr + c * 8);
        CP_COMMIT();
    }

    const int nk = D2 / 32;
    float4 na0, na1;
    for (int kk = 0; kk < nk; kk++) {
        const int buf = kk & 1, nxt = buf ^ 1;
        const bool has = (kk + 1) < nk;
        CP_WAIT0();
        __syncthreads();
        if (has) {
            const int k0 = (kk + 1) * 32;
#pragma unroll
            for (int c = 0; c < 4; c++)
                cpa16(uB + nxt * 16384 + sw_off(t, c), bptr + k0 + c * 8);
            CP_COMMIT();
            na0 = *(const float4*)(aptr + k0);
            na1 = *(const float4*)(aptr + k0 + 4);
        }
        const uint32_t bA = uA + buf * 4096, bB = uB + buf * 16384;
#pragma unroll
        for (int ks = 0; ks < 2; ks++) {
            uint32_t af[4][4], bf[2][4];
#pragma unroll
            for (int mf = 0; mf < 4; mf++)
                ldsm4(af[mf], bA + sw_off(mf * 16 + a_dm + tr, ks * 2 + a_dkc));
#pragma unroll
            for (int g2 = 0; g2 < 2; g2++)
                ldsm4(bf[g2], bB + sw_off(wn + g2 * 16 + b_dn + tr, ks * 2 + b_dkc));
#pragma unroll
            for (int mf = 0; mf < 4; mf++)
#pragma unroll
                for (int nf = 0; nf < 4; nf++)
                    mma16816(acc[mf][nf], af[mf], &bf[nf >> 1][(nf & 1) * 2]);
        }
        if (has) {
            uint4 av; cvt8(na0, na1, av);
            *(uint4*)((char*)sA[nxt] + staA) = av;
        }
    }

    const int rl = lane >> 2, cl = (lane & 3) * 2;
#pragma unroll
    for (int mf = 0; mf < 4; mf++) {
        float s0 = 0.f, q0 = 0.f, s1 = 0.f, q1 = 0.f;
#pragma unroll
        for (int nf = 0; nf < 4; nf++) {
            const int c = wn + cl + nf * 8;
            float v0 = acc[mf][nf][0] + sBias[c];
            float v1 = acc[mf][nf][1] + sBias[c + 1];
            float v2 = acc[mf][nf][2] + sBias[c];
            float v3 = acc[mf][nf][3] + sBias[c + 1];
            acc[mf][nf][0] = v0; acc[mf][nf][1] = v1;
            acc[mf][nf][2] = v2; acc[mf][nf][3] = v3;
            s0 += v0 + v1; q0 += v0 * v0 + v1 * v1;
            s1 += v2 + v3; q1 += v2 * v2 + v3 * v3;
        }
#pragma unroll
        for (int o = 1; o <= 2; o <<= 1) {
            s0 += __shfl_xor_sync(0xffffffffu, s0, o);
            q0 += __shfl_xor_sync(0xffffffffu, q0, o);
            s1 += __shfl_xor_sync(0xffffffffu, s1, o);
            q1 += __shfl_xor_sync(0xffffffffu, q1, o);
        }
        if ((lane & 3) == 0) {
            atomicAdd(&rsum[rl + mf * 16], s0);
            atomicAdd(&rsq [rl + mf * 16], q0);
            atomicAdd(&rsum[rl + mf * 16 + 8], s1);
            atomicAdd(&rsq [rl + mf * 16 + 8], q1);
        }
    }
    __syncthreads();
#pragma unroll
    for (int mf = 0; mf < 4; mf++) {
        const int r0 = rl + mf * 16, r1 = r0 + 8;
        const float m0 = rsum[r0] * (1.f / DD);
        const float i0 = rsqrtf(rsq[r0] * (1.f / DD) - m0 * m0 + EPS);
        const float m1 = rsum[r1] * (1.f / DD);
        const float i1 = rsqrtf(rsq[r1] * (1.f / DD) - m1 * m1 + EPS);
        __half* d0 = n1h + (size_t)(row0 + r0) * DD;
        __half* d1 = n1h + (size_t)(row0 + r1) * DD;
#pragma unroll
        for (int nf = 0; nf < 4; nf++) {
            const int c = wn + cl + nf * 8;
            __half2 h0 = __floats2half2_rn(
                (acc[mf][nf][0] - m0) * i0 * sG[c] + sBv[c],
                (acc[mf][nf][1] - m0) * i0 * sG[c + 1] + sBv[c + 1]);
            __half2 h1 = __floats2half2_rn(
                (acc[mf][nf][2] - m1) * i1 * sG[c] + sBv[c],
                (acc[mf][nf][3] - m1) * i1 * sG[c + 1] + sBv[c + 1]);
            *(__half2*)(d0 + c) = h0;
            *(__half2*)(d1 + c) = h1;
        }
    }
}

// ============ GEMM2 fused: out = x1 + LN(n1h @ W2eff[b] + b2) ================
// 512 threads, 16 warps (2m x 8n), warp tile 32x64. 2-stage cp.async.
#define G2_SA_ST  4096
#define G2_SB_ST  32768
#define G2_SA     0
#define G2_SB     (2 * G2_SA_ST)
#define G2_VEC    (G2_SB + 2 * G2_SB_ST)
#define G2_RED    (G2_VEC + 3 * 512 * 4)
#define G2_SMEM   (G2_RED + 2 * 64 * 4)

__global__ __launch_bounds__(512, 1) void gemm2_ln_k(
    const __half* __restrict__ n1h, const __half* __restrict__ b2,
    const float* __restrict__ bias, const float* __restrict__ g,
    const float* __restrict__ bvec, const float* __restrict__ x1,
    float* __restrict__ outp)
{
    extern __shared__ char smem[];
    const uint32_t uA = s2u(smem) + G2_SA;
    const uint32_t uB = s2u(smem) + G2_SB;
    float* sBias = (float*)(smem + G2_VEC);
    float* sG    = sBias + 512;
    float* sBv   = sG + 512;
    float* rsum  = (float*)(smem + G2_RED);
    float* rsq   = rsum + 64;

    const int t = threadIdx.x, lane = t & 31, wid = t >> 5;
    const int wm = (wid & 1) * 32;
    const int wn = (wid >> 1) * 64;
    const int row0 = blockIdx.x * 64;
    const int b = blockIdx.x >> 6;
    const __half* Bp = b2 + (size_t)b * D2 * DD;

    sBias[t] = bias[t]; sG[t] = g[t]; sBv[t] = bvec[t];
    if (t < 64) { rsum[t] = 0.f; rsq[t] = 0.f; }

    const int ar = t >> 2, aq = t & 3;      // A staging: threads 0..255
    const __half* aptr = n1h + (size_t)(row0 + ar) * DD + aq * 8;
    const uint32_t staA = sw_off(ar, aq);
    const __half* bptr = Bp + (size_t)t * DD;   // B row = t (0..511)

    float acc[2][8][4];
#pragma unroll
    for (int i = 0; i < 2; i++)
#pragma unroll
        for (int j = 0; j < 8; j++)
#pragma unroll
            for (int k = 0; k < 4; k++) acc[i][j][k] = 0.f;

    const int ti = lane >> 3, tr = lane & 7;
    const int a_dm = (ti & 1) * 8, a_dkc = ti >> 1;
    const int b_dn = (ti >> 1) * 8, b_dkc = ti & 1;

    {
        if (t < 256) cpa16(uA + staA, aptr);
#pragma unroll
        for (int c = 0; c < 4; c++)
            cpa16(uB + sw_off(t, c), bptr + c * 8);
        CP_COMMIT();
    }

    const int nk = DD / 32;    // 8
    for (int kk = 0; kk < nk; kk++) {
        const int buf = kk & 1, nxt = buf ^ 1;
        const bool has = (kk + 1) < nk;
        CP_WAIT0();
        __syncthreads();
        if (has) {
            const int k0 = (kk + 1) * 32;
            if (t < 256) cpa16(uA + nxt * G2_SA_ST + staA, aptr + k0);
#pragma unroll
            for (int c = 0; c < 4; c++)
                cpa16(uB + nxt * G2_SB_ST + sw_off(t, c), bptr + k0 + c * 8);
            CP_COMMIT();
        }
        const uint32_t bA = uA + buf * G2_SA_ST, bB = uB + buf * G2_SB_ST;
#pragma unroll
        for (int ks = 0; ks < 2; ks++) {
            uint32_t af[2][4], bf[4][4];
#pragma unroll
            for (int mf = 0; mf < 2; mf++)
                ldsm4(af[mf], bA + sw_off(wm + mf * 16 + a_dm + tr, ks * 2 + a_dkc));
#pragma unroll
            for (int g2 = 0; g2 < 4; g2++)
                ldsm4(bf[g2], bB + sw_off(wn + g2 * 16 + b_dn + tr, ks * 2 + b_dkc));
#pragma unroll
            for (int mf = 0; mf < 2; mf++)
#pragma unroll
                for (int nf = 0; nf < 8; nf++)
                    mma16816(acc[mf][nf], af[mf], &bf[nf >> 1][(nf & 1) * 2]);
        }
    }

    const int rl = lane >> 2, cl = (lane & 3) * 2;
#pragma unroll
    for (int mf = 0; mf < 2; mf++) {
        float s0 = 0.f, q0 = 0.f, s1 = 0.f, q1 = 0.f;
#pragma unroll
        for (int nf = 0; nf < 8; nf++) {
            const int c = wn + cl + nf * 8;
            float v0 = acc[mf][nf][0] + sBias[c];
            float v1 = acc[mf][nf][1] + sBias[c + 1];
            float v2 = acc[mf][nf][2] + sBias[c];
            float v3 = acc[mf][nf][3] + sBias[c + 1];
            acc[mf][nf][0] = v0; acc[mf][nf][1] = v1;
            acc[mf][nf][2] = v2; acc[mf][nf][3] = v3;
            s0 += v0 + v1; q0 += v0 * v0 + v1 * v1;
            s1 += v2 + v3; q1 += v2 * v2 + v3 * v3;
        }
#pragma unroll
        for (int o = 1; o <= 2; o <<= 1) {
            s0 += __shfl_xor_sync(0xffffffffu, s0, o);
            q0 += __shfl_xor_sync(0xffffffffu, q0, o);
            s1 += __shfl_xor_sync(0xffffffffu, s1, o);
            q1 += __shfl_xor_sync(0xffffffffu, q1, o);
        }
        if ((lane & 3) == 0) {
            atomicAdd(&rsum[wm + mf * 16 + rl], s0);
            atomicAdd(&rsq [wm + mf * 16 + rl], q0);
            atomicAdd(&rsum[wm + mf * 16 + rl + 8], s1);
            atomicAdd(&rsq [wm + mf * 16 + rl + 8], q1);
        }
    }
    __syncthreads();
#pragma unroll
    for (int mf = 0; mf < 2; mf++) {
        const int r0 = wm + mf * 16 + rl, r1 = r0 + 8;
        const float m0 = rsum[r0] * (1.f / D2);
        const float i0 = rsqrtf(rsq[r0] * (1.f / D2) - m0 * m0 + EPS);
        const float m1 = rsum[r1] * (1.f / D2);
        const float i1 = rsqrtf(rsq[r1] * (1.f / D2) - m1 * m1 + EPS);
        const float* x0 = x1 + (size_t)(row0 + r0) * D2;
        const float* x1p = x1 + (size_t)(row0 + r1) * D2;
        float* d0 = outp + (size_t)(row0 + r0) * D2;
        float* d1 = outp + (size_t)(row0 + r1) * D2;
#pragma unroll
        for (int nf = 0; nf < 8; nf++) {
            const int c = wn + cl + nf * 8;
            float2 xa = *(const float2*)(x0 + c);
            float2 xb = *(const float2*)(x1p + c);
            float2 o0, o1;
            o0.x = xa.x + (acc[mf][nf][0] - m0) * i0 * sG[c] + sBv[c];
            o0.y = xa.y + (acc[mf][nf][1] - m0) * i0 * sG[c + 1] + sBv[c + 1];
            o1.x = xb.x + (acc[mf][nf][2] - m1) * i1 * sG[c] + sBv[c];
            o1.y = xb.y + (acc[mf][nf][3] - m1) * i1 * sG[c + 1] + sBv[c + 1];
            *(float2*)(d0 + c) = o0;
            *(float2*)(d1 + c) = o1;
        }
    }
}

// ============ LN(x2) + exp + channel-softmax -> E, Y (fp16) ==================
// warp per token; lane covers 8 channels; head = lane>>2.
__global__ __launch_bounds__(256) void ln_exp_k(
    const float* __restrict__ x2, const float* __restrict__ g,
    const float* __restrict__ b, __half* __restrict__ Eg,
    __half* __restrict__ Yg)
{
    const int row  = (blockIdx.x * blockDim.x + threadIdx.x) >> 5;
    const int lane = threadIdx.x & 31;
    const float* p = x2 + (size_t)row * DD + lane * 8;
    float4 a = *(const float4*)p;
    float4 c = *(const float4*)(p + 4);

    float s = a.x + a.y + a.z + a.w + c.x + c.y + c.z + c.w;
#pragma unroll
    for (int o = 16; o; o >>= 1) s += __shfl_xor_sync(0xffffffffu, s, o);
    const float mean = s * (1.0f / DD);

    float ax = a.x - mean, ay = a.y - mean, az = a.z - mean, aw = a.w - mean;
    float cx = c.x - mean, cy = c.y - mean, cz = c.z - mean, cw = c.w - mean;
    float s2 = ax*ax + ay*ay + az*az + aw*aw + cx*cx + cy*cy + cz*cz + cw*cw;
#pragma unroll
    for (int o = 16; o; o >>= 1) s2 += __shfl_xor_sync(0xffffffffu, s2, o);
    const float rstd = rsqrtf(s2 * (1.0f / DD) + EPS);

    const int ci = lane * 8;
    float4 g0 = *(const float4*)(g + ci);
    float4 g1 = *(const float4*)(g + ci + 4);
    float4 b0 = *(const float4*)(b + ci);
    float4 b1 = *(const float4*)(b + ci + 4);

    float4 e0, e1;
    e0.x = __expf(ax*rstd*g0.x + b0.x); e0.y = __expf(ay*rstd*g0.y + b0.y);
    e0.z = __expf(az*rstd*g0.z + b0.z); e0.w = __expf(aw*rstd*g0.w + b0.w);
    e1.x = __expf(cx*rstd*g1.x + b1.x); e1.y = __expf(cy*rstd*g1.y + b1.y);
    e1.z = __expf(cz*rstd*g1.z + b1.z); e1.w = __expf(cw*rstd*g1.w + b1.w);

    float qs = e0.x + e0.y + e0.z + e0.w + e1.x + e1.y + e1.z + e1.w;
    qs += __shfl_xor_sync(0xffffffffu, qs, 1);
    qs += __shfl_xor_sync(0xffffffffu, qs, 2);   // per-head (4-lane group) sum
    const float inv = 1.0f / qs;

    float4 y0, y1;
    y0.x = e0.x * inv; y0.y = e0.y * inv; y0.z = e0.z * inv; y0.w = e0.w * inv;
    y1.x = e1.x * inv; y1.y = e1.y * inv; y1.z = e1.z * inv; y1.w = e1.w * inv;

    uint4 ev, yv;
    cvt8(e0, e1, ev);
    cvt8(y0, y1, yv);
    *(uint4*)(Eg + (size_t)row * DD + ci) = ev;
    *(uint4*)(Yg + (size_t)row * DD + ci) = yv;
}

// ============ ctx partials: S[d,e] = sum_n Y[n,d]*E[n,e] per (b,h) ===========
// grid (kc=8, bh=64). 256 thr: tp=t>>6 token-parity, 8x8 grid of 4x4 outputs.
__global__ __launch_bounds__(256) void ctx_ffma_k(
    const __half* __restrict__ Eg, const __half* __restrict__ Yg,
    float* __restrict__ Spart)
{
    __shared__ __align__(16) __half sE[2][128 * 32];
    __shared__ __align__(16) __half sY[2][128 * 32];

    const int kc = blockIdx.x, bh = blockIdx.y;
    const int b = bh >> 3, h = bh & 7;
    const int t = threadIdx.x;
    const int tp = t >> 6, r = t & 63, ty = r >> 3, tx = r & 7;

    const uint32_t uE = s2u(sE), uY = s2u(sY);
    const size_t gbase = (size_t)b * NN + kc * 512;

    float acc[4][4];
#pragma unroll
    for (int i = 0; i < 4; i++)
#pragma unroll
        for (int j = 0; j < 4; j++) acc[i][j] = 0.f;

    // stage sub-chunk (128 tokens) into buffer st
    auto stage = [&](int st, int sub) {
#pragma unroll
        for (int j = 0; j < 2; j++) {
            const int idx = t + j * 256;           // 0..511
            const int tok = idx >> 2, c4 = idx & 3;
            const size_t grow = gbase + sub * 128 + tok;
            cpa16(uE + st * 8192 + tok * 64 + c4 * 16,
                  Eg + grow * DD + h * DK + c4 * 8);
            cpa16(uY + st * 8192 + tok * 64 + c4 * 16,
                  Yg + grow * DD + h * DK + c4 * 8);
        }
        CP_COMMIT();
    };

    stage(0, 0);
    for (int sub = 0; sub < 4; sub++) {
        const int buf = sub & 1, nxt = buf ^ 1;
        CP_WAIT0();
        __syncthreads();
        if (sub < 3) stage(nxt, sub + 1);
#pragma unroll 4
        for (int n0 = 0; n0 < 128; n0 += 4) {
            const int n = n0 + tp;
            uint2 yv = *(const uint2*)&sY[buf][n * 32 + ty * 4];
            uint2 ev = *(const uint2*)&sE[buf][n * 32 + tx * 4];
            __half2 ya = *(__half2*)&yv.x, yb = *(__half2*)&yv.y;
            __half2 ea = *(__half2*)&ev.x, eb = *(__half2*)&ev.y;
            float yf[4] = {__low2float(ya), __high2float(ya),
                           __low2float(yb), __high2float(yb)};
            float ef[4] = {__low2float(ea), __high2float(ea),
                           __low2float(eb), __high2float(eb)};
#pragma unroll
            for (int i = 0; i < 4; i++)
#pragma unroll
                for (int j = 0; j < 4; j++) acc[i][j] += yf[i] * ef[j];
        }
        __syncthreads();
    }

    float* op = Spart + ((size_t)(kc * 4 + tp) * 64 + bh) * (DK * DK);
#pragma unroll
    for (int i = 0; i < 4; i++)
#pragma unroll
        for (int j = 0; j < 4; j++)
            op[(ty * 4 + i) * 32 + tx * 4 + j] = acc[i][j];
}

// ============ ksum: column sums of E =========================================
__global__ __launch_bounds__(256) void ksum_part_k(
    const __half* __restrict__ Eg, float* __restrict__ part)
{
    const int chunk = blockIdx.x, b = blockIdx.y, t = threadIdx.x;
    const __half* p = Eg + ((size_t)b * NN + chunk * 128) * DD + t;
    float s = 0.f;
#pragma unroll 8
    for (int n = 0; n < 128; n++) s += __half2float(p[(size_t)n * DD]);
    part[(b * 32 + chunk) * DD + t] = s;
}

__global__ void ksum_reduce_k(const float* __restrict__ part,
                              float* __restrict__ ksum)
{
    const int b = blockIdx.x, c = threadIdx.x;
    float s = 0.f;
#pragma unroll
    for (int j = 0; j < 32; j++) s += part[(b * 32 + j) * DD + c];
    ksum[b * DD + c] = s;
}

__global__ __launch_bounds__(1024) void ctx_final_k(
    const float* __restrict__ Spart, const float* __restrict__ ksum,
    float* __restrict__ ctx)
{
    const int bh = blockIdx.x;
    const int t  = threadIdx.x;
    const int b  = bh >> 3, h = bh & 7;
    const int e  = t & 31;
    float s = 0.f;
#pragma unroll
    for (int sl = 0; sl < 32; sl++)
        s += Spart[((size_t)sl * 64 + bh) * (DK * DK) + t];
    ctx[(size_t)bh * (DK * DK) + t] = s / ksum[b * DD + h * DK + e];
}

// ---------------- W2eff[b][o][c=h*32+e] = sum_d ctx[b,h,d,e]*rw[o][h*32+d] ---
__global__ __launch_bounds__(256) void w2eff_k(
    const float* __restrict__ ctx, const float* __restrict__ rw,
    __half* __restrict__ b2h)
{
    extern __shared__ float ws[];
    float* ctxs = ws;
    float* rws  = ws + 8192;
    const int b  = blockIdx.x;
    const int o0 = blockIdx.y * 32;
    const int t  = threadIdx.x;

    const float* cs = ctx + (size_t)b * HEADS * DK * DK;
    for (int i = t; i < HEADS * DK * DK; i += 256) ctxs[i] = cs[i];
    for (int i = t; i < 32 * 256; i += 256)
        rws[i] = rw[(size_t)(o0 + (i >> 8)) * DD + (i & 255)];
    __syncthreads();

    const int h = t >> 5, e = t & 31;
    const float* cbase = ctxs + h * (DK * DK) + e;
    for (int o = 0; o < 32; o++) {
        float acc = 0.f;
        const float* rb = rws + (o << 8) + h * DK;
#pragma unroll
        for (int d = 0; d < 32; d++) acc += cbase[d * 32] * rb[d];
        b2h[((size_t)b * D2 + o0 + o) * DD + t] = __float2half_rn(acc);
    }
}

// ---------------- W1 transpose + fp16 conversion -----------------------------
__global__ void convert_w1_k(const float* __restrict__ W,
                             __half* __restrict__ wh)
{
    __shared__ float tile[32][33];
    const int n0 = blockIdx.x * 32;
    const int k0 = blockIdx.y * 32;
    const int x = threadIdx.x, y = threadIdx.y;
#pragma unroll
    for (int i = 0; i < 32; i += 8)
        tile[y + i][x] = W[(size_t)(k0 + y + i) * DD + n0 + x];
    __syncthreads();
#pragma unroll
    for (int i = 0; i < 32; i += 8)
        wh[(size_t)(n0 + y + i) * D2 + k0 + x] = __float2half_rn(tile[x][y + i]);
}

// ---------------- host launch ------------------------------------------------
extern "C" void kernel_launch(void* const* d_in, const int* in_sizes, int n_in,
                              void* d_out, int out_size)
{
    const float* x1        = (const float*)d_in[0];
    const float* x2        = (const float*)d_in[1];
    const float* linear_w  = (const float*)d_in[2];
    const float* linear_b  = (const float*)d_in[3];
    const float* ln1_g     = (const float*)d_in[4];
    const float* ln1_b     = (const float*)d_in[5];
    const float* reproj_w  = (const float*)d_in[6];
    const float* reproj_b  = (const float*)d_in[7];
    const float* ln_attn_g = (const float*)d_in[8];
    const float* ln_attn_b = (const float*)d_in[9];
    float* out = (float*)d_out;

    float *part, *ksum, *Spart, *ctx;
    __half *n1h, *w1h, *b2h, *Eg, *Yg;
    cudaGetSymbolAddress((void**)&n1h,  g_n1h);
    cudaGetSymbolAddress((void**)&Eg,   g_E);
    cudaGetSymbolAddress((void**)&Yg,   g_Y);
    cudaGetSymbolAddress((void**)&w1h,  g_w1h);
    cudaGetSymbolAddress((void**)&b2h,  g_b2h);
    cudaGetSymbolAddress((void**)&part, g_part);
    cudaGetSymbolAddress((void**)&ksum, g_ksum);
    cudaGetSymbolAddress((void**)&Spart,g_Spart);
    cudaGetSymbolAddress((void**)&ctx,  g_ctx);

    cudaFuncSetAttribute(gemm2_ln_k, cudaFuncAttributeMaxDynamicSharedMemorySize,
                         G2_SMEM);
    cudaFuncSetAttribute(w2eff_k, cudaFuncAttributeMaxDynamicSharedMemorySize,
                         65536);

    // 1: LN(x2)+exp+channel softmax -> E, Y
    ln_exp_k<<<RR / 8, 256>>>(x2, ln1_g, ln1_b, Eg, Yg);
    // 2: W1 prep
    convert_w1_k<<<dim3(DD / 32, D2 / 32), dim3(32, 8)>>>(linear_w, w1h);
    // 3: ctx partials
    ctx_ffma_k<<<dim3(8, 64), 256>>>(Eg, Yg, Spart);
    // 4: GEMM1 fused (profiled slot)
    gemm1_ln_k<<<RR / 64, 256>>>(x1, w1h, linear_b, ln1_g, ln1_b, n1h);
    // 5-7: ksum + ctx
    ksum_part_k<<<dim3(32, Bb), 256>>>(Eg, part);
    ksum_reduce_k<<<Bb, DD>>>(part, ksum);
    ctx_final_k<<<Bb * HEADS, DK * DK>>>(Spart, ksum, ctx);
    // 8: effective reprojection weights
    w2eff_k<<<dim3(Bb, D2 / 32), 256, 65536>>>(ctx, reproj_w, b2h);
    // 9: GEMM2 fused
    gemm2_ln_k<<<RR / 64, 512, G2_SMEM>>>(n1h, b2h, reproj_b, ln_attn_g,
                                          ln_attn_b, x1, out);
}

// round 8
// speedup vs baseline: 1.4578x; 1.2970x over previous
#include <cuda_runtime.h>
#include <cuda_fp16.h>
#include <cstdint>
#include <math.h>

#define Bb     8
#define NN     4096
#define RR     32768
#define DD     256
#define D2     512
#define HEADS  8
#define DK     32
#define EPS    1e-5f

// ---------------- scratch (device globals; no runtime allocation) -----------
__device__ __align__(16) __half g_x1h [RR * D2];        // x1 in fp16
__device__ __align__(16) __half g_n1h [RR * DD];
__device__ __align__(16) __half g_E   [RR * DD];        // exp(LN(x2)) fp16
__device__ __align__(16) __half g_Y   [RR * DD];        // E/qsum fp16
__device__ __align__(16) __half g_w1h [DD * D2];        // W1^T [n][k] fp16
__device__ __align__(16) __half g_b2h [Bb * D2 * DD];   // W2eff [b][o][c] fp16
__device__ __align__(16) float  g_part [Bb * 32 * DD];
__device__ __align__(16) float  g_ksum [Bb * DD];
__device__ __align__(16) float  g_Spart[32 * Bb * HEADS * DK * DK];
__device__ __align__(16) float  g_ctx  [Bb * HEADS * DK * DK];

// ---------------- helpers ----------------------------------------------------
__device__ __forceinline__ uint32_t s2u(const void* p) {
    uint32_t a;
    asm("{ .reg .u64 t; cvta.to.shared.u64 t, %1; cvt.u32.u64 %0, t; }"
        : "=r"(a) : "l"(p));
    return a;
}
__device__ __forceinline__ void cvt8(const float4& a, const float4& b, uint4& o) {
    __half2 h0 = __floats2half2_rn(a.x, a.y);
    __half2 h1 = __floats2half2_rn(a.z, a.w);
    __half2 h2 = __floats2half2_rn(b.x, b.y);
    __half2 h3 = __floats2half2_rn(b.z, b.w);
    o.x = *reinterpret_cast<uint32_t*>(&h0);
    o.y = *reinterpret_cast<uint32_t*>(&h1);
    o.z = *reinterpret_cast<uint32_t*>(&h2);
    o.w = *reinterpret_cast<uint32_t*>(&h3);
}
__device__ __forceinline__ void ldsm4(uint32_t* r, uint32_t addr) {
    asm volatile("ldmatrix.sync.aligned.m8n8.x4.shared.b16 {%0,%1,%2,%3}, [%4];"
                 : "=r"(r[0]), "=r"(r[1]), "=r"(r[2]), "=r"(r[3]) : "r"(addr));
}
__device__ __forceinline__ void mma16816(float* c, const uint32_t* a,
                                         const uint32_t* b) {
    asm volatile(
        "mma.sync.aligned.m16n8k16.row.col.f32.f16.f16.f32 "
        "{%0,%1,%2,%3}, {%4,%5,%6,%7}, {%8,%9}, {%0,%1,%2,%3};"
        : "+f"(c[0]), "+f"(c[1]), "+f"(c[2]), "+f"(c[3])
        : "r"(a[0]), "r"(a[1]), "r"(a[2]), "r"(a[3]), "r"(b[0]), "r"(b[1]));
}
__device__ __forceinline__ void cpa16(uint32_t dst, const void* src) {
    asm volatile("cp.async.ca.shared.global [%0], [%1], 16;" :: "r"(dst), "l"(src));
}
#define CP_COMMIT() asm volatile("cp.async.commit_group;")
#define CP_WAIT0()  asm volatile("cp.async.wait_group 0;")
#define CP_WAIT1()  asm volatile("cp.async.wait_group 1;")

// swizzled byte offset: rows of 32 fp16 (64B), 4 chunks of 16B, XOR swizzle
__device__ __forceinline__ uint32_t sw_off(int row, int cch) {
    return (uint32_t)(row * 64 + ((cch ^ ((row >> 1) & 3)) << 4));
}

// ---------------- x1 -> fp16 -------------------------------------------------
__global__ __launch_bounds__(256) void convert_x1_k(
    const float* __restrict__ x1, __half* __restrict__ x1h)
{
    const size_t i = ((size_t)blockIdx.x * 256 + threadIdx.x) * 8;
    float4 a = *(const float4*)(x1 + i);
    float4 b = *(const float4*)(x1 + i + 4);
    uint4 v; cvt8(a, b, v);
    *(uint4*)(x1h + i) = v;
}

// ============ GEMM1 fused: n1h = fp16( LN(x1h @ W1 + b1) ) ===================
// CTA 128x256 (full LN rows), 512 thr, 16 warps 4m x 4n, warp 32x64.
// 3-stage cp.async pipeline, KC=32, K=512 (16 chunks).
#define G1_SA_ST 8192
#define G1_SB_ST 16384
#define G1_SB    (3 * G1_SA_ST)
#define G1_VEC   (G1_SB + 3 * G1_SB_ST)
#define G1_RED   (G1_VEC + 3 * 256 * 4)
#define G1_SMEM  (G1_RED + 2 * 128 * 4)

__global__ __launch_bounds__(512, 1) void gemm1_ln_k(
    const __half* __restrict__ x1h, const __half* __restrict__ w1,
    const float* __restrict__ bias, const float* __restrict__ g,
    const float* __restrict__ bvec, __half* __restrict__ n1h)
{
    extern __shared__ char smem[];
    const uint32_t uA = s2u(smem);
    const uint32_t uB = uA + G1_SB;
    float* sBias = (float*)(smem + G1_VEC);
    float* sG    = sBias + 256;
    float* sBv   = sG + 256;
    float* rsum  = (float*)(smem + G1_RED);
    float* rsq   = rsum + 128;

    const int t = threadIdx.x, lane = t & 31, wid = t >> 5;
    const int wm = (wid & 3) * 32;
    const int wn = (wid >> 2) * 64;
    const int row0 = blockIdx.x * 128;

    if (t < 256) { sBias[t] = bias[t]; sG[t] = g[t]; sBv[t] = bvec[t]; }
    if (t < 128) { rsum[t] = 0.f; rsq[t] = 0.f; }

    // staging maps
    const int ar = t >> 2, aq = t & 3;                 // A: 128 rows x 4 chunks
    const __half* aptr = x1h + (size_t)(row0 + ar) * D2 + aq * 8;
    const uint32_t staA = sw_off(ar, aq);

    float acc[2][8][4];
#pragma unroll
    for (int i = 0; i < 2; i++)
#pragma unroll
        for (int j = 0; j < 8; j++)
#pragma unroll
            for (int k = 0; k < 4; k++) acc[i][j][k] = 0.f;

    const int ti = lane >> 3, tr = lane & 7;
    const int a_dm = (ti & 1) * 8, a_dkc = ti >> 1;
    const int b_dn = (ti >> 1) * 8, b_dkc = ti & 1;

    auto stage = [&](int s, int kk) {
        const int k0 = kk * 32;
        cpa16(uA + s * G1_SA_ST + staA, aptr + k0);
#pragma unroll
        for (int j = 0; j < 2; j++) {
            const int idx = t + j * 512;               // B: 256 rows x 4 chunks
            const int br = idx >> 2, bq = idx & 3;
            cpa16(uB + s * G1_SB_ST + sw_off(br, bq),
                  w1 + (size_t)br * D2 + k0 + bq * 8);
        }
        CP_COMMIT();
    };

    stage(0, 0);
    stage(1, 1);

    const int nk = D2 / 32;    // 16
    for (int kk = 0; kk < nk; kk++) {
        CP_WAIT1();
        __syncthreads();
        if (kk + 2 < nk) stage((kk + 2) % 3, kk + 2);
        const int buf = kk % 3;
        const uint32_t bA = uA + buf * G1_SA_ST, bB = uB + buf * G1_SB_ST;
#pragma unroll
        for (int ks = 0; ks < 2; ks++) {
            uint32_t af[2][4], bf[4][4];
#pragma unroll
            for (int mf = 0; mf < 2; mf++)
                ldsm4(af[mf], bA + sw_off(wm + mf * 16 + a_dm + tr, ks * 2 + a_dkc));
#pragma unroll
            for (int g2 = 0; g2 < 4; g2++)
                ldsm4(bf[g2], bB + sw_off(wn + g2 * 16 + b_dn + tr, ks * 2 + b_dkc));
#pragma unroll
            for (int mf = 0; mf < 2; mf++)
#pragma unroll
                for (int nf = 0; nf < 8; nf++)
                    mma16816(acc[mf][nf], af[mf], &bf[nf >> 1][(nf & 1) * 2]);
        }
        __syncthreads();
    }

    // ---- epilogue: bias + LN over 256 cols, write fp16 ----
    const int rl = lane >> 2, cl = (lane & 3) * 2;
#pragma unroll
    for (int mf = 0; mf < 2; mf++) {
        float s0 = 0.f, q0 = 0.f, s1 = 0.f, q1 = 0.f;
#pragma unroll
        for (int nf = 0; nf < 8; nf++) {
            const int c = wn + cl + nf * 8;
            float v0 = acc[mf][nf][0] + sBias[c];
            float v1 = acc[mf][nf][1] + sBias[c + 1];
            float v2 = acc[mf][nf][2] + sBias[c];
            float v3 = acc[mf][nf][3] + sBias[c + 1];
            acc[mf][nf][0] = v0; acc[mf][nf][1] = v1;
            acc[mf][nf][2] = v2; acc[mf][nf][3] = v3;
            s0 += v0 + v1; q0 += v0 * v0 + v1 * v1;
            s1 += v2 + v3; q1 += v2 * v2 + v3 * v3;
        }
#pragma unroll
        for (int o = 1; o <= 2; o <<= 1) {
            s0 += __shfl_xor_sync(0xffffffffu, s0, o);
            q0 += __shfl_xor_sync(0xffffffffu, q0, o);
            s1 += __shfl_xor_sync(0xffffffffu, s1, o);
            q1 += __shfl_xor_sync(0xffffffffu, q1, o);
        }
        if ((lane & 3) == 0) {
            atomicAdd(&rsum[wm + mf * 16 + rl], s0);
            atomicAdd(&rsq [wm + mf * 16 + rl], q0);
            atomicAdd(&rsum[wm + mf * 16 + rl + 8], s1);
            atomicAdd(&rsq [wm + mf * 16 + rl + 8], q1);
        }
    }
    __syncthreads();
#pragma unroll
    for (int mf = 0; mf < 2; mf++) {
        const int r0 = wm + mf * 16 + rl, r1 = r0 + 8;
        const float m0 = rsum[r0] * (1.f / DD);
        const float i0 = rsqrtf(rsq[r0] * (1.f / DD) - m0 * m0 + EPS);
        const float m1 = rsum[r1] * (1.f / DD);
        const float i1 = rsqrtf(rsq[r1] * (1.f / DD) - m1 * m1 + EPS);
        __half* d0 = n1h + (size_t)(row0 + r0) * DD;
        __half* d1 = n1h + (size_t)(row0 + r1) * DD;
#pragma unroll
        for (int nf = 0; nf < 8; nf++) {
            const int c = wn + cl + nf * 8;
            __half2 h0 = __floats2half2_rn(
                (acc[mf][nf][0] - m0) * i0 * sG[c] + sBv[c],
                (acc[mf][nf][1] - m0) * i0 * sG[c + 1] + sBv[c + 1]);
            __half2 h1 = __floats2half2_rn(
                (acc[mf][nf][2] - m1) * i1 * sG[c] + sBv[c],
                (acc[mf][nf][3] - m1) * i1 * sG[c + 1] + sBv[c + 1]);
            *(__half2*)(d0 + c) = h0;
            *(__half2*)(d1 + c) = h1;
        }
    }
}

// ============ GEMM2 fused: out = x1 + LN(n1h @ W2eff[b] + b2) ================
// CTA 64x512, 512 thr, 16 warps 2m x 8n, warp 32x64. 3-stage cp.async, K=256.
#define G2_SA_ST  4096
#define G2_SB_ST  32768
#define G2_SB     (3 * G2_SA_ST)
#define G2_VEC    (G2_SB + 3 * G2_SB_ST)
#define G2_RED    (G2_VEC + 3 * 512 * 4)
#define G2_SMEM   (G2_RED + 2 * 64 * 4)

__global__ __launch_bounds__(512, 1) void gemm2_ln_k(
    const __half* __restrict__ n1h, const __half* __restrict__ b2,
    const float* __restrict__ bias, const float* __restrict__ g,
    const float* __restrict__ bvec, const float* __restrict__ x1,
    float* __restrict__ outp)
{
    extern __shared__ char smem[];
    const uint32_t uA = s2u(smem);
    const uint32_t uB = uA + G2_SB;
    float* sBias = (float*)(smem + G2_VEC);
    float* sG    = sBias + 512;
    float* sBv   = sG + 512;
    float* rsum  = (float*)(smem + G2_RED);
    float* rsq   = rsum + 64;

    const int t = threadIdx.x, lane = t & 31, wid = t >> 5;
    const int wm = (wid & 1) * 32;
    const int wn = (wid >> 1) * 64;
    const int row0 = blockIdx.x * 64;
    const int b = blockIdx.x >> 6;
    const __half* Bp = b2 + (size_t)b * D2 * DD;

    sBias[t] = bias[t]; sG[t] = g[t]; sBv[t] = bvec[t];
    if (t < 64) { rsum[t] = 0.f; rsq[t] = 0.f; }

    const int ar = t >> 2, aq = t & 3;
    const __half* aptr = n1h + (size_t)(row0 + ar) * DD + aq * 8;
    const uint32_t staA = sw_off(ar, aq);

    float acc[2][8][4];
#pragma unroll
    for (int i = 0; i < 2; i++)
#pragma unroll
        for (int j = 0; j < 8; j++)
#pragma unroll
            for (int k = 0; k < 4; k++) acc[i][j][k] = 0.f;

    const int ti = lane >> 3, tr = lane & 7;
    const int a_dm = (ti & 1) * 8, a_dkc = ti >> 1;
    const int b_dn = (ti >> 1) * 8, b_dkc = ti & 1;

    auto stage = [&](int s, int kk) {
        const int k0 = kk * 32;
        if (t < 256) cpa16(uA + s * G2_SA_ST + staA, aptr + k0);
#pragma unroll
        for (int j = 0; j < 4; j++) {
            const int idx = t + j * 512;               // B: 512 rows x 4 chunks
            const int br = idx >> 2, bq = idx & 3;
            cpa16(uB + s * G2_SB_ST + sw_off(br, bq),
                  Bp + (size_t)br * DD + k0 + bq * 8);
        }
        CP_COMMIT();
    };

    stage(0, 0);
    stage(1, 1);

    const int nk = DD / 32;    // 8
    for (int kk = 0; kk < nk; kk++) {
        CP_WAIT1();
        __syncthreads();
        if (kk + 2 < nk) stage((kk + 2) % 3, kk + 2);
        const int buf = kk % 3;
        const uint32_t bA = uA + buf * G2_SA_ST, bB = uB + buf * G2_SB_ST;
#pragma unroll
        for (int ks = 0; ks < 2; ks++) {
            uint32_t af[2][4], bf[4][4];
#pragma unroll
            for (int mf = 0; mf < 2; mf++)
                ldsm4(af[mf], bA + sw_off(wm + mf * 16 + a_dm + tr, ks * 2 + a_dkc));
#pragma unroll
            for (int g2 = 0; g2 < 4; g2++)
                ldsm4(bf[g2], bB + sw_off(wn + g2 * 16 + b_dn + tr, ks * 2 + b_dkc));
#pragma unroll
            for (int mf = 0; mf < 2; mf++)
#pragma unroll
                for (int nf = 0; nf < 8; nf++)
                    mma16816(acc[mf][nf], af[mf], &bf[nf >> 1][(nf & 1) * 2]);
        }
        __syncthreads();
    }

    const int rl = lane >> 2, cl = (lane & 3) * 2;
#pragma unroll
    for (int mf = 0; mf < 2; mf++) {
        float s0 = 0.f, q0 = 0.f, s1 = 0.f, q1 = 0.f;
#pragma unroll
        for (int nf = 0; nf < 8; nf++) {
            const int c = wn + cl + nf * 8;
            float v0 = acc[mf][nf][0] + sBias[c];
            float v1 = acc[mf][nf][1] + sBias[c + 1];
            float v2 = acc[mf][nf][2] + sBias[c];
            float v3 = acc[mf][nf][3] + sBias[c + 1];
            acc[mf][nf][0] = v0; acc[mf][nf][1] = v1;
            acc[mf][nf][2] = v2; acc[mf][nf][3] = v3;
            s0 += v0 + v1; q0 += v0 * v0 + v1 * v1;
            s1 += v2 + v3; q1 += v2 * v2 + v3 * v3;
        }
#pragma unroll
        for (int o = 1; o <= 2; o <<= 1) {
            s0 += __shfl_xor_sync(0xffffffffu, s0, o);
            q0 += __shfl_xor_sync(0xffffffffu, q0, o);
            s1 += __shfl_xor_sync(0xffffffffu, s1, o);
            q1 += __shfl_xor_sync(0xffffffffu, q1, o);
        }
        if ((lane & 3) == 0) {
            atomicAdd(&rsum[wm + mf * 16 + rl], s0);
            atomicAdd(&rsq [wm + mf * 16 + rl], q0);
            atomicAdd(&rsum[wm + mf * 16 + rl + 8], s1);
            atomicAdd(&rsq [wm + mf * 16 + rl + 8], q1);
        }
    }
    __syncthreads();
#pragma unroll
    for (int mf = 0; mf < 2; mf++) {
        const int r0 = wm + mf * 16 + rl, r1 = r0 + 8;
        const float m0 = rsum[r0] * (1.f / D2);
        const float i0 = rsqrtf(rsq[r0] * (1.f / D2) - m0 * m0 + EPS);
        const float m1 = rsum[r1] * (1.f / D2);
        const float i1 = rsqrtf(rsq[r1] * (1.f / D2) - m1 * m1 + EPS);
        const float* x0 = x1 + (size_t)(row0 + r0) * D2;
        const float* x1p = x1 + (size_t)(row0 + r1) * D2;
        float* d0 = outp + (size_t)(row0 + r0) * D2;
        float* d1 = outp + (size_t)(row0 + r1) * D2;
#pragma unroll
        for (int nf = 0; nf < 8; nf++) {
            const int c = wn + cl + nf * 8;
            float2 xa = *(const float2*)(x0 + c);
            float2 xb = *(const float2*)(x1p + c);
            float2 o0, o1;
            o0.x = xa.x + (acc[mf][nf][0] - m0) * i0 * sG[c] + sBv[c];
            o0.y = xa.y + (acc[mf][nf][1] - m0) * i0 * sG[c + 1] + sBv[c + 1];
            o1.x = xb.x + (acc[mf][nf][2] - m1) * i1 * sG[c] + sBv[c];
            o1.y = xb.y + (acc[mf][nf][3] - m1) * i1 * sG[c + 1] + sBv[c + 1];
            *(float2*)(d0 + c) = o0;
            *(float2*)(d1 + c) = o1;
        }
    }
}

// ============ LN(x2) + exp + channel-softmax -> E, Y (fp16) ==================
__global__ __launch_bounds__(256) void ln_exp_k(
    const float* __restrict__ x2, const float* __restrict__ g,
    const float* __restrict__ b, __half* __restrict__ Eg,
    __half* __restrict__ Yg)
{
    const int row  = (blockIdx.x * blockDim.x + threadIdx.x) >> 5;
    const int lane = threadIdx.x & 31;
    const float* p = x2 + (size_t)row * DD + lane * 8;
    float4 a = *(const float4*)p;
    float4 c = *(const float4*)(p + 4);

    float s = a.x + a.y + a.z + a.w + c.x + c.y + c.z + c.w;
#pragma unroll
    for (int o = 16; o; o >>= 1) s += __shfl_xor_sync(0xffffffffu, s, o);
    const float mean = s * (1.0f / DD);

    float ax = a.x - mean, ay = a.y - mean, az = a.z - mean, aw = a.w - mean;
    float cx = c.x - mean, cy = c.y - mean, cz = c.z - mean, cw = c.w - mean;
    float s2 = ax*ax + ay*ay + az*az + aw*aw + cx*cx + cy*cy + cz*cz + cw*cw;
#pragma unroll
    for (int o = 16; o; o >>= 1) s2 += __shfl_xor_sync(0xffffffffu, s2, o);
    const float rstd = rsqrtf(s2 * (1.0f / DD) + EPS);

    const int ci = lane * 8;
    float4 g0 = *(const float4*)(g + ci);
    float4 g1 = *(const float4*)(g + ci + 4);
    float4 b0 = *(const float4*)(b + ci);
    float4 b1 = *(const float4*)(b + ci + 4);

    float4 e0, e1;
    e0.x = __expf(ax*rstd*g0.x + b0.x); e0.y = __expf(ay*rstd*g0.y + b0.y);
    e0.z = __expf(az*rstd*g0.z + b0.z); e0.w = __expf(aw*rstd*g0.w + b0.w);
    e1.x = __expf(cx*rstd*g1.x + b1.x); e1.y = __expf(cy*rstd*g1.y + b1.y);
    e1.z = __expf(cz*rstd*g1.z + b1.z); e1.w = __expf(cw*rstd*g1.w + b1.w);

    float qs = e0.x + e0.y + e0.z + e0.w + e1.x + e1.y + e1.z + e1.w;
    qs += __shfl_xor_sync(0xffffffffu, qs, 1);
    qs += __shfl_xor_sync(0xffffffffu, qs, 2);
    const float inv = 1.0f / qs;

    float4 y0, y1;
    y0.x = e0.x * inv; y0.y = e0.y * inv; y0.z = e0.z * inv; y0.w = e0.w * inv;
    y1.x = e1.x * inv; y1.y = e1.y * inv; y1.z = e1.z * inv; y1.w = e1.w * inv;

    uint4 ev, yv;
    cvt8(e0, e1, ev);
    cvt8(y0, y1, yv);
    *(uint4*)(Eg + (size_t)row * DD + ci) = ev;
    *(uint4*)(Yg + (size_t)row * DD + ci) = yv;
}

// ============ ctx partials ===================================================
__global__ __launch_bounds__(256) void ctx_ffma_k(
    const __half* __restrict__ Eg, const __half* __restrict__ Yg,
    float* __restrict__ Spart)
{
    __shared__ __align__(16) __half sE[2][128 * 32];
    __shared__ __align__(16) __half sY[2][128 * 32];

    const int kc = blockIdx.x, bh = blockIdx.y;
    const int b = bh >> 3, h = bh & 7;
    const int t = threadIdx.x;
    const int tp = t >> 6, r = t & 63, ty = r >> 3, tx = r & 7;

    const uint32_t uE = s2u(sE), uY = s2u(sY);
    const size_t gbase = (size_t)b * NN + kc * 512;

    float acc[4][4];
#pragma unroll
    for (int i = 0; i < 4; i++)
#pragma unroll
        for (int j = 0; j < 4; j++) acc[i][j] = 0.f;

    auto stage = [&](int st, int sub) {
#pragma unroll
        for (int j = 0; j < 2; j++) {
            const int idx = t + j * 256;
            const int tok = idx >> 2, c4 = idx & 3;
            const size_t grow = gbase + sub * 128 + tok;
            cpa16(uE + st * 8192 + tok * 64 + c4 * 16,
                  Eg + grow * DD + h * DK + c4 * 8);
            cpa16(uY + st * 8192 + tok * 64 + c4 * 16,
                  Yg + grow * DD + h * DK + c4 * 8);
        }
        CP_COMMIT();
    };

    stage(0, 0);
    for (int sub = 0; sub < 4; sub++) {
        const int buf = sub & 1, nxt = buf ^ 1;
        CP_WAIT0();
        __syncthreads();
        if (sub < 3) stage(nxt, sub + 1);
#pragma unroll 4
        for (int n0 = 0; n0 < 128; n0 += 4) {
            const int n = n0 + tp;
            uint2 yv = *(const uint2*)&sY[buf][n * 32 + ty * 4];
            uint2 ev = *(const uint2*)&sE[buf][n * 32 + tx * 4];
            __half2 ya = *(__half2*)&yv.x, yb = *(__half2*)&yv.y;
            __half2 ea = *(__half2*)&ev.x, eb = *(__half2*)&ev.y;
            float yf[4] = {__low2float(ya), __high2float(ya),
                           __low2float(yb), __high2float(yb)};
            float ef[4] = {__low2float(ea), __high2float(ea),
                           __low2float(eb), __high2float(eb)};
#pragma unroll
            for (int i = 0; i < 4; i++)
#pragma unroll
                for (int j = 0; j < 4; j++) acc[i][j] += yf[i] * ef[j];
        }
        __syncthreads();
    }

    float* op = Spart + ((size_t)(kc * 4 + tp) * 64 + bh) * (DK * DK);
#pragma unroll
    for (int i = 0; i < 4; i++)
#pragma unroll
        for (int j = 0; j < 4; j++)
            op[(ty * 4 + i) * 32 + tx * 4 + j] = acc[i][j];
}

// ============ ksum ===========================================================
__global__ __launch_bounds__(256) void ksum_part_k(
    const __half* __restrict__ Eg, float* __restrict__ part)
{
    const int chunk = blockIdx.x, b = blockIdx.y, t = threadIdx.x;
    const __half* p = Eg + ((size_t)b * NN + chunk * 128) * DD + t;
    float s = 0.f;
#pragma unroll 8
    for (int n = 0; n < 128; n++) s += __half2float(p[(size_t)n * DD]);
    part[(b * 32 + chunk) * DD + t] = s;
}

__global__ void ksum_reduce_k(const float* __restrict__ part,
                              float* __restrict__ ksum)
{
    const int b = blockIdx.x, c = threadIdx.x;
    float s = 0.f;
#pragma unroll
    for (int j = 0; j < 32; j++) s += part[(b * 32 + j) * DD + c];
    ksum[b * DD + c] = s;
}

__global__ __launch_bounds__(1024) void ctx_final_k(
    const float* __restrict__ Spart, const float* __restrict__ ksum,
    float* __restrict__ ctx)
{
    const int bh = blockIdx.x;
    const int t  = threadIdx.x;
    const int b  = bh >> 3, h = bh & 7;
    const int e  = t & 31;
    float s = 0.f;
#pragma unroll
    for (int sl = 0; sl < 32; sl++)
        s += Spart[((size_t)sl * 64 + bh) * (DK * DK) + t];
    ctx[(size_t)bh * (DK * DK) + t] = s / ksum[b * DD + h * DK + e];
}

// ---------------- W2eff ------------------------------------------------------
__global__ __launch_bounds__(256) void w2eff_k(
    const float* __restrict__ ctx, const float* __restrict__ rw,
    __half* __restrict__ b2h)
{
    extern __shared__ float ws[];
    float* ctxs = ws;
    float* rws  = ws + 8192;
    const int b  = blockIdx.x;
    const int o0 = blockIdx.y * 32;
    const int t  = threadIdx.x;

    const float* cs = ctx + (size_t)b * HEADS * DK * DK;
    for (int i = t; i < HEADS * DK * DK; i += 256) ctxs[i] = cs[i];
    for (int i = t; i < 32 * 256; i += 256)
        rws[i] = rw[(size_t)(o0 + (i >> 8)) * DD + (i & 255)];
    __syncthreads();

    const int h = t >> 5, e = t & 31;
    const float* cbase = ctxs + h * (DK * DK) + e;
    for (int o = 0; o < 32; o++) {
        float acc = 0.f;
        const float* rb = rws + (o << 8) + h * DK;
#pragma unroll
        for (int d = 0; d < 32; d++) acc += cbase[d * 32] * rb[d];
        b2h[((size_t)b * D2 + o0 + o) * DD + t] = __float2half_rn(acc);
    }
}

// ---------------- W1 transpose + fp16 ----------------------------------------
__global__ void convert_w1_k(const float* __restrict__ W,
                             __half* __restrict__ wh)
{
    __shared__ float tile[32][33];
    const int n0 = blockIdx.x * 32;
    const int k0 = blockIdx.y * 32;
    const int x = threadIdx.x, y = threadIdx.y;
#pragma unroll
    for (int i = 0; i < 32; i += 8)
        tile[y + i][x] = W[(size_t)(k0 + y + i) * DD + n0 + x];
    __syncthreads();
#pragma unroll
    for (int i = 0; i < 32; i += 8)
        wh[(size_t)(n0 + y + i) * D2 + k0 + x] = __float2half_rn(tile[x][y + i]);
}

// ---------------- host launch ------------------------------------------------
extern "C" void kernel_launch(void* const* d_in, const int* in_sizes, int n_in,
                              void* d_out, int out_size)
{
    const float* x1        = (const float*)d_in[0];
    const float* x2        = (const float*)d_in[1];
    const float* linear_w  = (const float*)d_in[2];
    const float* linear_b  = (const float*)d_in[3];
    const float* ln1_g     = (const float*)d_in[4];
    const float* ln1_b     = (const float*)d_in[5];
    const float* reproj_w  = (const float*)d_in[6];
    const float* reproj_b  = (const float*)d_in[7];
    const float* ln_attn_g = (const float*)d_in[8];
    const float* ln_attn_b = (const float*)d_in[9];
    float* out = (float*)d_out;

    float *part, *ksum, *Spart, *ctx;
    __half *x1h, *n1h, *w1h, *b2h, *Eg, *Yg;
    cudaGetSymbolAddress((void**)&x1h,  g_x1h);
    cudaGetSymbolAddress((void**)&n1h,  g_n1h);
    cudaGetSymbolAddress((void**)&Eg,   g_E);
    cudaGetSymbolAddress((void**)&Yg,   g_Y);
    cudaGetSymbolAddress((void**)&w1h,  g_w1h);
    cudaGetSymbolAddress((void**)&b2h,  g_b2h);
    cudaGetSymbolAddress((void**)&part, g_part);
    cudaGetSymbolAddress((void**)&ksum, g_ksum);
    cudaGetSymbolAddress((void**)&Spart,g_Spart);
    cudaGetSymbolAddress((void**)&ctx,  g_ctx);

    cudaFuncSetAttribute(gemm1_ln_k, cudaFuncAttributeMaxDynamicSharedMemorySize,
                         G1_SMEM);
    cudaFuncSetAttribute(gemm2_ln_k, cudaFuncAttributeMaxDynamicSharedMemorySize,
                         G2_SMEM);
    cudaFuncSetAttribute(w2eff_k, cudaFuncAttributeMaxDynamicSharedMemorySize,
                         65536);

    // 1: x1 -> fp16
    convert_x1_k<<<RR * D2 / (256 * 8), 256>>>(x1, x1h);
    // 2: W1 prep
    convert_w1_k<<<dim3(DD / 32, D2 / 32), dim3(32, 8)>>>(linear_w, w1h);
    // 3: LN(x2)+exp+softmax
    ln_exp_k<<<RR / 8, 256>>>(x2, ln1_g, ln1_b, Eg, Yg);
    // 4: GEMM1 fused (profiled slot)
    gemm1_ln_k<<<RR / 128, 512, G1_SMEM>>>(x1h, w1h, linear_b, ln1_g, ln1_b, n1h);
    // 5: ctx partials
    ctx_ffma_k<<<dim3(8, 64), 256>>>(Eg, Yg, Spart);
    // 6-8: ksum + ctx
    ksum_part_k<<<dim3(32, Bb), 256>>>(Eg, part);
    ksum_reduce_k<<<Bb, DD>>>(part, ksum);
    ctx_final_k<<<Bb * HEADS, DK * DK>>>(Spart, ksum, ctx);
    // 9: effective reprojection weights
    w2eff_k<<<dim3(Bb, D2 / 32), 256, 65536>>>(ctx, reproj_w, b2h);
    // 10: GEMM2 fused
    gemm2_ln_k<<<RR / 64, 512, G2_SMEM>>>(n1h, b2h, reproj_b, ln_attn_g,
                                          ln_attn_b, x1, out);
}

// round 9
// speedup vs baseline: 1.6337x; 1.1207x over previous
#include <cuda_runtime.h>
#include <cuda_fp16.h>
#include <cstdint>
#include <math.h>

#define Bb     8
#define NN     4096
#define RR     32768
#define DD     256
#define D2     512
#define HEADS  8
#define DK     32
#define EPS    1e-5f

// ---------------- scratch (device globals; no runtime allocation) -----------
__device__ __align__(16) __half g_x1h [RR * D2];        // x1 in fp16
__device__ __align__(16) __half g_n1h [RR * DD];
__device__ __align__(16) __half g_E   [RR * DD];        // exp(LN(x2)) fp16
__device__ __align__(16) __half g_Y   [RR * DD];        // E/qsum fp16
__device__ __align__(16) __half g_w1h [DD * D2];        // W1^T [n][k] fp16
__device__ __align__(16) __half g_b2h [Bb * D2 * DD];   // W2eff [b][o][c] fp16
__device__ __align__(16) float  g_Spart[4 * Bb * HEADS * DK * DK];
__device__ __align__(16) float  g_ctx  [Bb * HEADS * DK * DK];

// ---------------- helpers ----------------------------------------------------
__device__ __forceinline__ uint32_t s2u(const void* p) {
    uint32_t a;
    asm("{ .reg .u64 t; cvta.to.shared.u64 t, %1; cvt.u32.u64 %0, t; }"
        : "=r"(a) : "l"(p));
    return a;
}
__device__ __forceinline__ void cvt8(const float4& a, const float4& b, uint4& o) {
    __half2 h0 = __floats2half2_rn(a.x, a.y);
    __half2 h1 = __floats2half2_rn(a.z, a.w);
    __half2 h2 = __floats2half2_rn(b.x, b.y);
    __half2 h3 = __floats2half2_rn(b.z, b.w);
    o.x = *reinterpret_cast<uint32_t*>(&h0);
    o.y = *reinterpret_cast<uint32_t*>(&h1);
    o.z = *reinterpret_cast<uint32_t*>(&h2);
    o.w = *reinterpret_cast<uint32_t*>(&h3);
}
__device__ __forceinline__ void ldsm4(uint32_t* r, uint32_t addr) {
    asm volatile("ldmatrix.sync.aligned.m8n8.x4.shared.b16 {%0,%1,%2,%3}, [%4];"
                 : "=r"(r[0]), "=r"(r[1]), "=r"(r[2]), "=r"(r[3]) : "r"(addr));
}
__device__ __forceinline__ void ldsm4t(uint32_t* r, uint32_t addr) {
    asm volatile("ldmatrix.sync.aligned.m8n8.x4.trans.shared.b16 {%0,%1,%2,%3}, [%4];"
                 : "=r"(r[0]), "=r"(r[1]), "=r"(r[2]), "=r"(r[3]) : "r"(addr));
}
__device__ __forceinline__ void mma16816(float* c, const uint32_t* a,
                                         const uint32_t* b) {
    asm volatile(
        "mma.sync.aligned.m16n8k16.row.col.f32.f16.f16.f32 "
        "{%0,%1,%2,%3}, {%4,%5,%6,%7}, {%8,%9}, {%0,%1,%2,%3};"
        : "+f"(c[0]), "+f"(c[1]), "+f"(c[2]), "+f"(c[3])
        : "r"(a[0]), "r"(a[1]), "r"(a[2]), "r"(a[3]), "r"(b[0]), "r"(b[1]));
}
__device__ __forceinline__ void cpa16(uint32_t dst, const void* src) {
    asm volatile("cp.async.ca.shared.global [%0], [%1], 16;" :: "r"(dst), "l"(src));
}
#define CP_COMMIT() asm volatile("cp.async.commit_group;")
#define CP_WAIT0()  asm volatile("cp.async.wait_group 0;")
#define CP_WAIT1()  asm volatile("cp.async.wait_group 1;")

// swizzled byte offset: rows of 32 fp16 (64B), 4 chunks of 16B, XOR swizzle
__device__ __forceinline__ uint32_t sw_off(int row, int cch) {
    return (uint32_t)(row * 64 + ((cch ^ ((row >> 1) & 3)) << 4));
}

// ============ prep: x1->fp16 AND LN(x2)+exp+softmax -> E,Y ===================
// 256 thr = 8 warps; warp w handles row blockIdx*8+w for both jobs.
__global__ __launch_bounds__(256) void prep_k(
    const float* __restrict__ x1, const float* __restrict__ x2,
    const float* __restrict__ g, const float* __restrict__ b,
    __half* __restrict__ x1h, __half* __restrict__ Eg, __half* __restrict__ Yg)
{
    const int row  = blockIdx.x * 8 + (threadIdx.x >> 5);
    const int lane = threadIdx.x & 31;

    // ---- convert x1 row (512 floats; 16 per lane) ----
    {
        const float* xp = x1 + (size_t)row * D2 + lane * 16;
        float4 a0 = *(const float4*)xp;
        float4 a1 = *(const float4*)(xp + 4);
        float4 a2 = *(const float4*)(xp + 8);
        float4 a3 = *(const float4*)(xp + 12);
        uint4 v0, v1;
        cvt8(a0, a1, v0);
        cvt8(a2, a3, v1);
        __half* dp = x1h + (size_t)row * D2 + lane * 16;
        *(uint4*)dp       = v0;
        *(uint4*)(dp + 8) = v1;
    }

    // ---- LN(x2) + exp + channel softmax ----
    const float* p = x2 + (size_t)row * DD + lane * 8;
    float4 a = *(const float4*)p;
    float4 c = *(const float4*)(p + 4);

    float s = a.x + a.y + a.z + a.w + c.x + c.y + c.z + c.w;
#pragma unroll
    for (int o = 16; o; o >>= 1) s += __shfl_xor_sync(0xffffffffu, s, o);
    const float mean = s * (1.0f / DD);

    float ax = a.x - mean, ay = a.y - mean, az = a.z - mean, aw = a.w - mean;
    float cx = c.x - mean, cy = c.y - mean, cz = c.z - mean, cw = c.w - mean;
    float s2 = ax*ax + ay*ay + az*az + aw*aw + cx*cx + cy*cy + cz*cz + cw*cw;
#pragma unroll
    for (int o = 16; o; o >>= 1) s2 += __shfl_xor_sync(0xffffffffu, s2, o);
    const float rstd = rsqrtf(s2 * (1.0f / DD) + EPS);

    const int ci = lane * 8;
    float4 g0 = *(const float4*)(g + ci);
    float4 g1 = *(const float4*)(g + ci + 4);
    float4 b0 = *(const float4*)(b + ci);
    float4 b1 = *(const float4*)(b + ci + 4);

    float4 e0, e1;
    e0.x = __expf(ax*rstd*g0.x + b0.x); e0.y = __expf(ay*rstd*g0.y + b0.y);
    e0.z = __expf(az*rstd*g0.z + b0.z); e0.w = __expf(aw*rstd*g0.w + b0.w);
    e1.x = __expf(cx*rstd*g1.x + b1.x); e1.y = __expf(cy*rstd*g1.y + b1.y);
    e1.z = __expf(cz*rstd*g1.z + b1.z); e1.w = __expf(cw*rstd*g1.w + b1.w);

    float qs = e0.x + e0.y + e0.z + e0.w + e1.x + e1.y + e1.z + e1.w;
    qs += __shfl_xor_sync(0xffffffffu, qs, 1);
    qs += __shfl_xor_sync(0xffffffffu, qs, 2);   // per-head (4-lane) sum
    const float inv = 1.0f / qs;

    float4 y0, y1;
    y0.x = e0.x * inv; y0.y = e0.y * inv; y0.z = e0.z * inv; y0.w = e0.w * inv;
    y1.x = e1.x * inv; y1.y = e1.y * inv; y1.z = e1.z * inv; y1.w = e1.w * inv;

    uint4 ev, yv;
    cvt8(e0, e1, ev);
    cvt8(y0, y1, yv);
    *(uint4*)(Eg + (size_t)row * DD + ci) = ev;
    *(uint4*)(Yg + (size_t)row * DD + ci) = yv;
}

// ============ GEMM1 fused: n1h = fp16( LN(x1h @ W1 + b1) ) ===================
#define G1_SA_ST 8192
#define G1_SB_ST 16384
#define G1_SB    (3 * G1_SA_ST)
#define G1_VEC   (G1_SB + 3 * G1_SB_ST)
#define G1_RED   (G1_VEC + 3 * 256 * 4)
#define G1_SMEM  (G1_RED + 2 * 128 * 4)

__global__ __launch_bounds__(512, 1) void gemm1_ln_k(
    const __half* __restrict__ x1h, const __half* __restrict__ w1,
    const float* __restrict__ bias, const float* __restrict__ g,
    const float* __restrict__ bvec, __half* __restrict__ n1h)
{
    extern __shared__ char smem[];
    const uint32_t uA = s2u(smem);
    const uint32_t uB = uA + G1_SB;
    float* sBias = (float*)(smem + G1_VEC);
    float* sG    = sBias + 256;
    float* sBv   = sG + 256;
    float* rsum  = (float*)(smem + G1_RED);
    float* rsq   = rsum + 128;

    const int t = threadIdx.x, lane = t & 31, wid = t >> 5;
    const int wm = (wid & 3) * 32;
    const int wn = (wid >> 2) * 64;
    const int row0 = blockIdx.x * 128;

    if (t < 256) { sBias[t] = bias[t]; sG[t] = g[t]; sBv[t] = bvec[t]; }
    if (t < 128) { rsum[t] = 0.f; rsq[t] = 0.f; }

    const int ar = t >> 2, aq = t & 3;
    const __half* aptr = x1h + (size_t)(row0 + ar) * D2 + aq * 8;
    const uint32_t staA = sw_off(ar, aq);

    float acc[2][8][4];
#pragma unroll
    for (int i = 0; i < 2; i++)
#pragma unroll
        for (int j = 0; j < 8; j++)
#pragma unroll
            for (int k = 0; k < 4; k++) acc[i][j][k] = 0.f;

    const int ti = lane >> 3, tr = lane & 7;
    const int a_dm = (ti & 1) * 8, a_dkc = ti >> 1;
    const int b_dn = (ti >> 1) * 8, b_dkc = ti & 1;

    auto stage = [&](int s, int kk) {
        const int k0 = kk * 32;
        cpa16(uA + s * G1_SA_ST + staA, aptr + k0);
#pragma unroll
        for (int j = 0; j < 2; j++) {
            const int idx = t + j * 512;
            const int br = idx >> 2, bq = idx & 3;
            cpa16(uB + s * G1_SB_ST + sw_off(br, bq),
                  w1 + (size_t)br * D2 + k0 + bq * 8);
        }
        CP_COMMIT();
    };

    stage(0, 0);
    stage(1, 1);

    const int nk = D2 / 32;
    for (int kk = 0; kk < nk; kk++) {
        CP_WAIT1();
        __syncthreads();
        if (kk + 2 < nk) stage((kk + 2) % 3, kk + 2);
        const int buf = kk % 3;
        const uint32_t bA = uA + buf * G1_SA_ST, bB = uB + buf * G1_SB_ST;
#pragma unroll
        for (int ks = 0; ks < 2; ks++) {
            uint32_t af[2][4], bf[4][4];
#pragma unroll
            for (int mf = 0; mf < 2; mf++)
                ldsm4(af[mf], bA + sw_off(wm + mf * 16 + a_dm + tr, ks * 2 + a_dkc));
#pragma unroll
            for (int g2 = 0; g2 < 4; g2++)
                ldsm4(bf[g2], bB + sw_off(wn + g2 * 16 + b_dn + tr, ks * 2 + b_dkc));
#pragma unroll
            for (int mf = 0; mf < 2; mf++)
#pragma unroll
                for (int nf = 0; nf < 8; nf++)
                    mma16816(acc[mf][nf], af[mf], &bf[nf >> 1][(nf & 1) * 2]);
        }
    }

    // ---- epilogue: bias + LN over 256 cols, write fp16 ----
    const int rl = lane >> 2, cl = (lane & 3) * 2;
#pragma unroll
    for (int mf = 0; mf < 2; mf++) {
        float s0 = 0.f, q0 = 0.f, s1 = 0.f, q1 = 0.f;
#pragma unroll
        for (int nf = 0; nf < 8; nf++) {
            const int c = wn + cl + nf * 8;
            float v0 = acc[mf][nf][0] + sBias[c];
            float v1 = acc[mf][nf][1] + sBias[c + 1];
            float v2 = acc[mf][nf][2] + sBias[c];
            float v3 = acc[mf][nf][3] + sBias[c + 1];
            acc[mf][nf][0] = v0; acc[mf][nf][1] = v1;
            acc[mf][nf][2] = v2; acc[mf][nf][3] = v3;
            s0 += v0 + v1; q0 += v0 * v0 + v1 * v1;
            s1 += v2 + v3; q1 += v2 * v2 + v3 * v3;
        }
#pragma unroll
        for (int o = 1; o <= 2; o <<= 1) {
            s0 += __shfl_xor_sync(0xffffffffu, s0, o);
            q0 += __shfl_xor_sync(0xffffffffu, q0, o);
            s1 += __shfl_xor_sync(0xffffffffu, s1, o);
            q1 += __shfl_xor_sync(0xffffffffu, q1, o);
        }
        if ((lane & 3) == 0) {
            atomicAdd(&rsum[wm + mf * 16 + rl], s0);
            atomicAdd(&rsq [wm + mf * 16 + rl], q0);
            atomicAdd(&rsum[wm + mf * 16 + rl + 8], s1);
            atomicAdd(&rsq [wm + mf * 16 + rl + 8], q1);
        }
    }
    __syncthreads();
#pragma unroll
    for (int mf = 0; mf < 2; mf++) {
        const int r0 = wm + mf * 16 + rl, r1 = r0 + 8;
        const float m0 = rsum[r0] * (1.f / DD);
        const float i0 = rsqrtf(rsq[r0] * (1.f / DD) - m0 * m0 + EPS);
        const float m1 = rsum[r1] * (1.f / DD);
        const float i1 = rsqrtf(rsq[r1] * (1.f / DD) - m1 * m1 + EPS);
        __half* d0 = n1h + (size_t)(row0 + r0) * DD;
        __half* d1 = n1h + (size_t)(row0 + r1) * DD;
#pragma unroll
        for (int nf = 0; nf < 8; nf++) {
            const int c = wn + cl + nf * 8;
            __half2 h0 = __floats2half2_rn(
                (acc[mf][nf][0] - m0) * i0 * sG[c] + sBv[c],
                (acc[mf][nf][1] - m0) * i0 * sG[c + 1] + sBv[c + 1]);
            __half2 h1 = __floats2half2_rn(
                (acc[mf][nf][2] - m1) * i1 * sG[c] + sBv[c],
                (acc[mf][nf][3] - m1) * i1 * sG[c + 1] + sBv[c + 1]);
            *(__half2*)(d0 + c) = h0;
            *(__half2*)(d1 + c) = h1;
        }
    }
}

// ============ ctx via HMMA: S[d,e] = sum_n Y[n,d] E[n,e] per (b,h) ===========
// grid (4, 64): 1024 tokens per block. 256 thr = 8 warps; warp w owns token
// slice w*16..w*16+15 of each staged 128-token sub-tile.
__global__ __launch_bounds__(256) void ctx_mma_k(
    const __half* __restrict__ Eg, const __half* __restrict__ Yg,
    float* __restrict__ Spart)
{
    __shared__ __align__(16) __half sY[2][128 * 32];
    __shared__ __align__(16) __half sE[2][128 * 32];
    __shared__ float sS[32 * 32];

    const int kc = blockIdx.x, bh = blockIdx.y;
    const int b = bh >> 3, h = bh & 7;
    const int t = threadIdx.x, lane = t & 31, w = t >> 5;

    for (int i = t; i < 1024; i += 256) sS[i] = 0.f;

    const uint32_t uY = s2u(sY), uE = s2u(sE);
    const size_t gbase = (size_t)b * NN + kc * 1024;

    float acc[2][4][4];
#pragma unroll
    for (int m = 0; m < 2; m++)
#pragma unroll
        for (int n = 0; n < 4; n++)
#pragma unroll
            for (int k = 0; k < 4; k++) acc[m][n][k] = 0.f;

    auto stage = [&](int st, int sub) {
#pragma unroll
        for (int j = 0; j < 2; j++) {
            const int idx = t + j * 256;            // 0..511: (tok, chunk)
            const int tok = idx >> 2, c4 = idx & 3;
            const size_t grow = gbase + sub * 128 + tok;
            cpa16(uY + st * 8192 + sw_off(tok, c4),
                  Yg + grow * DD + h * DK + c4 * 8);
            cpa16(uE + st * 8192 + sw_off(tok, c4),
                  Eg + grow * DD + h * DK + c4 * 8);
        }
        CP_COMMIT();
    };

    // ldmatrix.trans lane addressing (within warp's 16-token slice)
    const int tb = w * 16;
    const int aTok = tb + (lane & 7) + ((lane >> 4) & 1) * 8;  // A: Y^T frags
    const int aChB = (lane >> 3) & 1;
    const int bTok = tb + (lane & 7) + ((lane >> 3) & 1) * 8;  // B: E^T frags
    const int bChB = (lane >> 4) & 1;

    stage(0, 0);
    for (int sub = 0; sub < 8; sub++) {
        const int buf = sub & 1, nxt = buf ^ 1;
        CP_WAIT0();
        __syncthreads();
        if (sub < 7) stage(nxt, sub + 1);

        const uint32_t uYb = uY + buf * 8192, uEb = uE + buf * 8192;
        uint32_t aY[2][4], bE[2][4];
#pragma unroll
        for (int m = 0; m < 2; m++)
            ldsm4t(aY[m], uYb + sw_off(aTok, m * 2 + aChB));
#pragma unroll
        for (int eh = 0; eh < 2; eh++)
            ldsm4t(bE[eh], uEb + sw_off(bTok, eh * 2 + bChB));
#pragma unroll
        for (int m = 0; m < 2; m++)
#pragma unroll
            for (int n = 0; n < 4; n++)
                mma16816(acc[m][n], aY[m], &bE[n >> 1][(n & 1) * 2]);
    }

    // cross-warp reduce into sS
    const int dg = lane >> 2, e0 = (lane & 3) * 2;
#pragma unroll
    for (int m = 0; m < 2; m++)
#pragma unroll
        for (int n = 0; n < 4; n++) {
            const int d = m * 16 + dg, e = n * 8 + e0;
            atomicAdd(&sS[d * 32 + e],           acc[m][n][0]);
            atomicAdd(&sS[d * 32 + e + 1],       acc[m][n][1]);
            atomicAdd(&sS[(d + 8) * 32 + e],     acc[m][n][2]);
            atomicAdd(&sS[(d + 8) * 32 + e + 1], acc[m][n][3]);
        }
    __syncthreads();

    float* op = Spart + ((size_t)(kc * 64) + bh) * (DK * DK);
#pragma unroll
    for (int i = 0; i < 4; i++)
        op[t + i * 256] = sS[t + i * 256];
}

// ============ ctx final: sum slices, ksum = column sums, divide ==============
__global__ __launch_bounds__(1024) void ctx_final_k(
    const float* __restrict__ Spart, float* __restrict__ ctx)
{
    __shared__ float sS[1024];
    __shared__ float sK[32];
    const int bh = blockIdx.x;
    const int t  = threadIdx.x;
    float s = 0.f;
#pragma unroll
    for (int sl = 0; sl < 4; sl++)
        s += Spart[((size_t)sl * 64 + bh) * 1024 + t];
    sS[t] = s;
    __syncthreads();
    if (t < 32) {
        float k = 0.f;
#pragma unroll
        for (int d = 0; d < 32; d++) k += sS[d * 32 + t];
        sK[t] = k;
    }
    __syncthreads();
    ctx[(size_t)bh * 1024 + t] = s / sK[t & 31];
}

// ---------------- W2eff[b][o][c=h*32+e] = sum_d ctx[b,h,d,e]*rw[o][h*32+d] ---
__global__ __launch_bounds__(256) void w2eff_k(
    const float* __restrict__ ctx, const float* __restrict__ rw,
    __half* __restrict__ b2h)
{
    extern __shared__ float ws[];
    float* ctxs = ws;
    float* rws  = ws + 8192;
    const int b  = blockIdx.x;
    const int o0 = blockIdx.y * 32;
    const int t  = threadIdx.x;

    const float* cs = ctx + (size_t)b * HEADS * DK * DK;
    for (int i = t; i < HEADS * DK * DK; i += 256) ctxs[i] = cs[i];
    for (int i = t; i < 32 * 256; i += 256)
        rws[i] = rw[(size_t)(o0 + (i >> 8)) * DD + (i & 255)];
    __syncthreads();

    const int h = t >> 5, e = t & 31;
    const float* cbase = ctxs + h * (DK * DK) + e;
    for (int o = 0; o < 32; o++) {
        float acc = 0.f;
        const float* rb = rws + (o << 8) + h * DK;
#pragma unroll
        for (int d = 0; d < 32; d++) acc += cbase[d * 32] * rb[d];
        b2h[((size_t)b * D2 + o0 + o) * DD + t] = __float2half_rn(acc);
    }
}

// ---------------- W1 transpose + fp16 ----------------------------------------
__global__ void convert_w1_k(const float* __restrict__ W,
                             __half* __restrict__ wh)
{
    __shared__ float tile[32][33];
    const int n0 = blockIdx.x * 32;
    const int k0 = blockIdx.y * 32;
    const int x = threadIdx.x, y = threadIdx.y;
#pragma unroll
    for (int i = 0; i < 32; i += 8)
        tile[y + i][x] = W[(size_t)(k0 + y + i) * DD + n0 + x];
    __syncthreads();
#pragma unroll
    for (int i = 0; i < 32; i += 8)
        wh[(size_t)(n0 + y + i) * D2 + k0 + x] = __float2half_rn(tile[x][y + i]);
}

// ============ GEMM2 fused: out = x1 + LN(n1h @ W2eff[b] + b2) ================
#define G2_SA_ST  4096
#define G2_SB_ST  32768
#define G2_SB     (3 * G2_SA_ST)
#define G2_VEC    (G2_SB + 3 * G2_SB_ST)
#define G2_RED    (G2_VEC + 3 * 512 * 4)
#define G2_SMEM   (G2_RED + 2 * 64 * 4)

__global__ __launch_bounds__(512, 1) void gemm2_ln_k(
    const __half* __restrict__ n1h, const __half* __restrict__ b2,
    const float* __restrict__ bias, const float* __restrict__ g,
    const float* __restrict__ bvec, const float* __restrict__ x1,
    float* __restrict__ outp)
{
    extern __shared__ char smem[];
    const uint32_t uA = s2u(smem);
    const uint32_t uB = uA + G2_SB;
    float* sBias = (float*)(smem + G2_VEC);
    float* sG    = sBias + 512;
    float* sBv   = sG + 512;
    float* rsum  = (float*)(smem + G2_RED);
    float* rsq   = rsum + 64;

    const int t = threadIdx.x, lane = t & 31, wid = t >> 5;
    const int wm = (wid & 1) * 32;
    const int wn = (wid >> 1) * 64;
    const int row0 = blockIdx.x * 64;
    const int b = blockIdx.x >> 6;
    const __half* Bp = b2 + (size_t)b * D2 * DD;

    sBias[t] = bias[t]; sG[t] = g[t]; sBv[t] = bvec[t];
    if (t < 64) { rsum[t] = 0.f; rsq[t] = 0.f; }

    const int ar = t >> 2, aq = t & 3;
    const __half* aptr = n1h + (size_t)(row0 + ar) * DD + aq * 8;
    const uint32_t staA = sw_off(ar, aq);

    float acc[2][8][4];
#pragma unroll
    for (int i = 0; i < 2; i++)
#pragma unroll
        for (int j = 0; j < 8; j++)
#pragma unroll
            for (int k = 0; k < 4; k++) acc[i][j][k] = 0.f;

    const int ti = lane >> 3, tr = lane & 7;
    const int a_dm = (ti & 1) * 8, a_dkc = ti >> 1;
    const int b_dn = (ti >> 1) * 8, b_dkc = ti & 1;

    auto stage = [&](int s, int kk) {
        const int k0 = kk * 32;
        if (t < 256) cpa16(uA + s * G2_SA_ST + staA, aptr + k0);
#pragma unroll
        for (int j = 0; j < 4; j++) {
            const int idx = t + j * 512;
            const int br = idx >> 2, bq = idx & 3;
            cpa16(uB + s * G2_SB_ST + sw_off(br, bq),
                  Bp + (size_t)br * DD + k0 + bq * 8);
        }
        CP_COMMIT();
    };

    stage(0, 0);
    stage(1, 1);

    const int nk = DD / 32;
    for (int kk = 0; kk < nk; kk++) {
        CP_WAIT1();
        __syncthreads();
        if (kk + 2 < nk) stage((kk + 2) % 3, kk + 2);
        const int buf = kk % 3;
        const uint32_t bA = uA + buf * G2_SA_ST, bB = uB + buf * G2_SB_ST;
#pragma unroll
        for (int ks = 0; ks < 2; ks++) {
            uint32_t af[2][4], bf[4][4];
#pragma unroll
            for (int mf = 0; mf < 2; mf++)
                ldsm4(af[mf], bA + sw_off(wm + mf * 16 + a_dm + tr, ks * 2 + a_dkc));
#pragma unroll
            for (int g2 = 0; g2 < 4; g2++)
                ldsm4(bf[g2], bB + sw_off(wn + g2 * 16 + b_dn + tr, ks * 2 + b_dkc));
#pragma unroll
            for (int mf = 0; mf < 2; mf++)
#pragma unroll
                for (int nf = 0; nf < 8; nf++)
                    mma16816(acc[mf][nf], af[mf], &bf[nf >> 1][(nf & 1) * 2]);
        }
    }

    const int rl = lane >> 2, cl = (lane & 3) * 2;
#pragma unroll
    for (int mf = 0; mf < 2; mf++) {
        float s0 = 0.f, q0 = 0.f, s1 = 0.f, q1 = 0.f;
#pragma unroll
        for (int nf = 0; nf < 8; nf++) {
            const int c = wn + cl + nf * 8;
            float v0 = acc[mf][nf][0] + sBias[c];
            float v1 = acc[mf][nf][1] + sBias[c + 1];
            float v2 = acc[mf][nf][2] + sBias[c];
            float v3 = acc[mf][nf][3] + sBias[c + 1];
            acc[mf][nf][0] = v0; acc[mf][nf][1] = v1;
            acc[mf][nf][2] = v2; acc[mf][nf][3] = v3;
            s0 += v0 + v1; q0 += v0 * v0 + v1 * v1;
            s1 += v2 + v3; q1 += v2 * v2 + v3 * v3;
        }
#pragma unroll
        for (int o = 1; o <= 2; o <<= 1) {
            s0 += __shfl_xor_sync(0xffffffffu, s0, o);
            q0 += __shfl_xor_sync(0xffffffffu, q0, o);
            s1 += __shfl_xor_sync(0xffffffffu, s1, o);
            q1 += __shfl_xor_sync(0xffffffffu, q1, o);
        }
        if ((lane & 3) == 0) {
            atomicAdd(&rsum[wm + mf * 16 + rl], s0);
            atomicAdd(&rsq [wm + mf * 16 + rl], q0);
            atomicAdd(&rsum[wm + mf * 16 + rl + 8], s1);
            atomicAdd(&rsq [wm + mf * 16 + rl + 8], q1);
        }
    }
    __syncthreads();
#pragma unroll
    for (int mf = 0; mf < 2; mf++) {
        const int r0 = wm + mf * 16 + rl, r1 = r0 + 8;
        const float m0 = rsum[r0] * (1.f / D2);
        const float i0 = rsqrtf(rsq[r0] * (1.f / D2) - m0 * m0 + EPS);
        const float m1 = rsum[r1] * (1.f / D2);
        const float i1 = rsqrtf(rsq[r1] * (1.f / D2) - m1 * m1 + EPS);
        const float* x0 = x1 + (size_t)(row0 + r0) * D2;
        const float* x1p = x1 + (size_t)(row0 + r1) * D2;
        float* d0 = outp + (size_t)(row0 + r0) * D2;
        float* d1 = outp + (size_t)(row0 + r1) * D2;
#pragma unroll
        for (int nf = 0; nf < 8; nf++) {
            const int c = wn + cl + nf * 8;
            float2 xa = *(const float2*)(x0 + c);
            float2 xb = *(const float2*)(x1p + c);
            float2 o0, o1;
            o0.x = xa.x + (acc[mf][nf][0] - m0) * i0 * sG[c] + sBv[c];
            o0.y = xa.y + (acc[mf][nf][1] - m0) * i0 * sG[c + 1] + sBv[c + 1];
            o1.x = xb.x + (acc[mf][nf][2] - m1) * i1 * sG[c] + sBv[c];
            o1.y = xb.y + (acc[mf][nf][3] - m1) * i1 * sG[c + 1] + sBv[c + 1];
            *(float2*)(d0 + c) = o0;
            *(float2*)(d1 + c) = o1;
        }
    }
}

// ---------------- host launch ------------------------------------------------
extern "C" void kernel_launch(void* const* d_in, const int* in_sizes, int n_in,
                              void* d_out, int out_size)
{
    const float* x1        = (const float*)d_in[0];
    const float* x2        = (const float*)d_in[1];
    const float* linear_w  = (const float*)d_in[2];
    const float* linear_b  = (const float*)d_in[3];
    const float* ln1_g     = (const float*)d_in[4];
    const float* ln1_b     = (const float*)d_in[5];
    const float* reproj_w  = (const float*)d_in[6];
    const float* reproj_b  = (const float*)d_in[7];
    const float* ln_attn_g = (const float*)d_in[8];
    const float* ln_attn_b = (const float*)d_in[9];
    float* out = (float*)d_out;

    float *Spart, *ctx;
    __half *x1h, *n1h, *w1h, *b2h, *Eg, *Yg;
    cudaGetSymbolAddress((void**)&x1h,  g_x1h);
    cudaGetSymbolAddress((void**)&n1h,  g_n1h);
    cudaGetSymbolAddress((void**)&Eg,   g_E);
    cudaGetSymbolAddress((void**)&Yg,   g_Y);
    cudaGetSymbolAddress((void**)&w1h,  g_w1h);
    cudaGetSymbolAddress((void**)&b2h,  g_b2h);
    cudaGetSymbolAddress((void**)&Spart,g_Spart);
    cudaGetSymbolAddress((void**)&ctx,  g_ctx);

    cudaFuncSetAttribute(gemm1_ln_k, cudaFuncAttributeMaxDynamicSharedMemorySize,
                         G1_SMEM);
    cudaFuncSetAttribute(gemm2_ln_k, cudaFuncAttributeMaxDynamicSharedMemorySize,
                         G2_SMEM);
    cudaFuncSetAttribute(w2eff_k, cudaFuncAttributeMaxDynamicSharedMemorySize,
                         65536);

    // 1: merged prep (x1->fp16, LN(x2)+exp+softmax -> E,Y)
    prep_k<<<RR / 8, 256>>>(x1, x2, ln1_g, ln1_b, x1h, Eg, Yg);
    // 2: W1 prep
    convert_w1_k<<<dim3(DD / 32, D2 / 32), dim3(32, 8)>>>(linear_w, w1h);
    // 3: GEMM1 fused
    gemm1_ln_k<<<RR / 128, 512, G1_SMEM>>>(x1h, w1h, linear_b, ln1_g, ln1_b, n1h);
    // 4: ctx partials via HMMA (profiled slot)
    ctx_mma_k<<<dim3(4, 64), 256>>>(Eg, Yg, Spart);
    // 5: ctx final (+ksum from column sums)
    ctx_final_k<<<Bb * HEADS, 1024>>>(Spart, ctx);
    // 6: effective reprojection weights
    w2eff_k<<<dim3(Bb, D2 / 32), 256, 65536>>>(ctx, reproj_w, b2h);
    // 7: GEMM2 fused
    gemm2_ln_k<<<RR / 64, 512, G2_SMEM>>>(n1h, b2h, reproj_b, ln_attn_g,
                                          ln_attn_b, x1, out);
}